// round 1
// baseline (speedup 1.0000x reference)
#include <cuda_runtime.h>
#include <math.h>

#define B 8
#define T 512
#define VOC 256
#define C 512
#define DFF 2048
#define H 8
#define LYR 6
#define KS 3
#define W 4
#define DK 64
#define NREL 9  // 2W+1

// ---------------- scratch (device globals; no allocation allowed) ------------
__device__ float g_h[B*C*T];      // residual stream [B,C,T]
__device__ float g_q[B*C*T];
__device__ float g_k[B*C*T];
__device__ float g_v[B*C*T];
__device__ float g_ctx[B*C*T];
__device__ float g_y[B*C*T];
__device__ float g_p[(size_t)B*H*T*T]; // attention probs / scores (64MB)
__device__ float g_f[B*DFF*T];    // FFN hidden (32MB)
__device__ float g_mask[B*T];

// ---------------- embedding + mask ------------------------------------------
__global__ void k_embed(const int* __restrict__ x, const int* __restrict__ xlen,
                        const float* __restrict__ emb,
                        float* __restrict__ out_xemb, float* __restrict__ out_mask) {
    int b = blockIdx.y;
    int t = blockIdx.x * 32 + threadIdx.x;
    int xi = x[b*T + t];
    float mk = (t < xlen[b]) ? 1.f : 0.f;
    const float SQ = 22.627416997969522f; // sqrt(512)
    for (int c = threadIdx.y; c < C; c += 8) {
        float v = emb[xi*C + c] * SQ;
        out_xemb[((size_t)b*C + c)*T + t] = v;
        g_h[((size_t)b*C + c)*T + t] = v * mk;
    }
    if (threadIdx.y == 0) {
        g_mask[b*T + t] = mk;
        out_mask[b*T + t] = mk;
    }
}

__global__ void k_maskh() {
    int idx = blockIdx.x * 256 + threadIdx.x;
    int t = idx % T;
    int b = idx / (C*T);
    g_h[idx] *= g_mask[b*T + t];
}

__global__ void k_oen(float* __restrict__ out1) {
    int idx = blockIdx.x * 256 + threadIdx.x;
    int t = idx % T;
    int b = idx / (C*T);
    out1[idx] = g_h[idx] * g_mask[b*T + t];
}

// ---------------- conv1x1 GEMM: Y[b,o,t] = sum_c W[o,c] X[b,c,t] + bias ------
// 64x64 tile, 16x16 threads, 4x4 register block.
__global__ void k_gemm1x1(const float* __restrict__ Wm, const float* __restrict__ bias,
                          const float* __restrict__ X, float* __restrict__ Y,
                          int O, int Cin, float scale, int maskIn, int maskOut) {
    __shared__ float Ws[64][33];
    __shared__ float Xs[32][65];
    int tx = threadIdx.x, ty = threadIdx.y;
    int lid = ty*16 + tx;
    int t0 = blockIdx.x*64, o0 = blockIdx.y*64, b = blockIdx.z;
    const float* Xb = X + (size_t)b*Cin*T;
    float acc[4][4] = {};
    for (int c0 = 0; c0 < Cin; c0 += 32) {
        for (int e = lid; e < 2048; e += 256) {
            int r = e >> 5, cc = e & 31;
            Ws[r][cc] = Wm[(size_t)(o0+r)*Cin + c0 + cc];
        }
        for (int e = lid; e < 2048; e += 256) {
            int r = e >> 6, cc = e & 63;
            float v = Xb[(size_t)(c0+r)*T + t0 + cc];
            if (maskIn) v *= g_mask[b*T + t0 + cc];
            Xs[r][cc] = v;
        }
        __syncthreads();
#pragma unroll
        for (int kk = 0; kk < 32; kk++) {
            float wv[4], xv[4];
#pragma unroll
            for (int i = 0; i < 4; i++) wv[i] = Ws[ty*4+i][kk];
#pragma unroll
            for (int j = 0; j < 4; j++) xv[j] = Xs[kk][tx + 16*j];
#pragma unroll
            for (int i = 0; i < 4; i++)
#pragma unroll
                for (int j = 0; j < 4; j++) acc[i][j] += wv[i]*xv[j];
        }
        __syncthreads();
    }
#pragma unroll
    for (int i = 0; i < 4; i++) {
        int o = o0 + ty*4 + i;
        float bi = bias[o];
#pragma unroll
        for (int j = 0; j < 4; j++) {
            int t = t0 + tx + 16*j;
            float r = (acc[i][j] + bi) * scale;
            if (maskOut) r *= g_mask[b*T + t];
            Y[((size_t)b*O + o)*T + t] = r;
        }
    }
}

// ---------------- conv1d K=3 same-pad: Y[b,o,t]=sum_{c,k} W[o,c,k] Xm[b,c,t+k-1]
__global__ void k_conv3(const float* __restrict__ Wm, const float* __restrict__ bias,
                        const float* __restrict__ X, float* __restrict__ Y,
                        int O, int Cin, int doRelu, int maskOut) {
    __shared__ float Ws[64][97];   // [o][cc*3+k]
    __shared__ float Xs[32][67];   // cols: t0-1 .. t0+64
    int tx = threadIdx.x, ty = threadIdx.y;
    int lid = ty*16 + tx;
    int t0 = blockIdx.x*64, o0 = blockIdx.y*64, b = blockIdx.z;
    const float* Xb = X + (size_t)b*Cin*T;
    float acc[4][4] = {};
    for (int c0 = 0; c0 < Cin; c0 += 32) {
        for (int e = lid; e < 6144; e += 256) {
            int r = e / 96, j = e % 96;
            Ws[r][j] = Wm[(size_t)(o0+r)*Cin*3 + c0*3 + j];
        }
        for (int e = lid; e < 2112; e += 256) {
            int r = e / 66, cc = e % 66;
            int tg = t0 + cc - 1;
            float v = 0.f;
            if (tg >= 0 && tg < T)
                v = Xb[(size_t)(c0+r)*T + tg] * g_mask[b*T + tg];
            Xs[r][cc] = v;
        }
        __syncthreads();
#pragma unroll
        for (int cc = 0; cc < 32; cc++) {
            float wv[4][3];
#pragma unroll
            for (int i = 0; i < 4; i++)
#pragma unroll
                for (int k = 0; k < 3; k++) wv[i][k] = Ws[ty*4+i][cc*3+k];
#pragma unroll
            for (int j = 0; j < 4; j++) {
                int col = tx + 16*j;
                float x0 = Xs[cc][col], x1 = Xs[cc][col+1], x2 = Xs[cc][col+2];
#pragma unroll
                for (int i = 0; i < 4; i++)
                    acc[i][j] += wv[i][0]*x0 + wv[i][1]*x1 + wv[i][2]*x2;
            }
        }
        __syncthreads();
    }
#pragma unroll
    for (int i = 0; i < 4; i++) {
        int o = o0 + ty*4 + i;
        float bi = bias[o];
#pragma unroll
        for (int j = 0; j < 4; j++) {
            int t = t0 + tx + 16*j;
            float r = acc[i][j] + bi;
            if (doRelu) r = fmaxf(r, 0.f);
            if (maskOut) r *= g_mask[b*T + t];
            Y[((size_t)b*O + o)*T + t] = r;
        }
    }
}

// ---------------- scores = q @ k^T (q,k in [B,C,T], d-major) -----------------
__global__ void k_qk(const float* __restrict__ q, const float* __restrict__ k,
                     float* __restrict__ p) {
    __shared__ float Qs[32][65];
    __shared__ float Ks[32][65];
    int tx = threadIdx.x, ty = threadIdx.y;
    int lid = ty*16 + tx;
    int s0 = blockIdx.x*64, t0 = blockIdx.y*64;
    int bh = blockIdx.z, b = bh >> 3, h = bh & 7;
    const float* qb = q + ((size_t)b*C + h*DK)*T;
    const float* kb = k + ((size_t)b*C + h*DK)*T;
    float acc[4][4] = {};
    for (int d0 = 0; d0 < DK; d0 += 32) {
        for (int e = lid; e < 2048; e += 256) {
            int dd = e >> 6, tt = e & 63;
            Qs[dd][tt] = qb[(size_t)(d0+dd)*T + t0 + tt];
        }
        for (int e = lid; e < 2048; e += 256) {
            int dd = e >> 6, ss = e & 63;
            Ks[dd][ss] = kb[(size_t)(d0+dd)*T + s0 + ss];
        }
        __syncthreads();
#pragma unroll
        for (int kk = 0; kk < 32; kk++) {
            float qv[4], kv[4];
#pragma unroll
            for (int i = 0; i < 4; i++) qv[i] = Qs[kk][ty*4+i];
#pragma unroll
            for (int j = 0; j < 4; j++) kv[j] = Ks[kk][tx + 16*j];
#pragma unroll
            for (int i = 0; i < 4; i++)
#pragma unroll
                for (int j = 0; j < 4; j++) acc[i][j] += qv[i]*kv[j];
        }
        __syncthreads();
    }
#pragma unroll
    for (int i = 0; i < 4; i++) {
        int t = t0 + ty*4 + i;
#pragma unroll
        for (int j = 0; j < 4; j++) {
            int s = s0 + tx + 16*j;
            p[((size_t)bh*T + t)*T + s] = acc[i][j];
        }
    }
}

// ---------------- relative band: p[t,s] += q[t]·rel_k[s-t+W], |s-t|<=W -------
__global__ void k_relband(const float* __restrict__ q, float* __restrict__ p,
                          const float* __restrict__ rk) {
    __shared__ float qs[32][65];
    __shared__ float rks[NREL][64];
    int b = blockIdx.z, h = blockIdx.y, t0 = blockIdx.x*32;
    int lid = threadIdx.y*32 + threadIdx.x;
    const float* qb = q + ((size_t)b*C + h*DK)*T;
    for (int e = lid; e < 2048; e += 256) {
        int d = e >> 5, tt = e & 31;
        qs[tt][d] = qb[(size_t)d*T + t0 + tt];
    }
    for (int e = lid; e < NREL*64; e += 256) rks[e/64][e%64] = rk[e];
    __syncthreads();
    for (int w = lid; w < 32*NREL; w += 256) {
        int trow = w / NREL, dt = w % NREL;
        int t = t0 + trow, s = t + dt - W;
        if (s >= 0 && s < T) {
            float dot = 0.f;
#pragma unroll
            for (int d = 0; d < 64; d++) dot += qs[trow][d]*rks[dt][d];
            p[(((size_t)(b*H + h))*T + t)*T + s] += dot;
        }
    }
}

// ---------------- masked softmax over s --------------------------------------
__global__ void k_softmax(float* __restrict__ p) {
    int t = blockIdx.x, h = blockIdx.y, b = blockIdx.z;
    float* row = p + (((size_t)(b*H + h))*T + t)*T;
    int tid = threadIdx.x;
    float mt = g_mask[b*T + t];
    float v[2];
#pragma unroll
    for (int r = 0; r < 2; r++) {
        int s = tid + r*256;
        float sc = row[s];
        if (mt * g_mask[b*T + s] == 0.f) sc = -1e4f;
        v[r] = sc;
    }
    __shared__ float red[256];
    red[tid] = fmaxf(v[0], v[1]);
    __syncthreads();
    for (int o = 128; o > 0; o >>= 1) {
        if (tid < o) red[tid] = fmaxf(red[tid], red[tid+o]);
        __syncthreads();
    }
    float mx = red[0];
    __syncthreads();
    float e0 = expf(v[0]-mx), e1 = expf(v[1]-mx);
    red[tid] = e0 + e1;
    __syncthreads();
    for (int o = 128; o > 0; o >>= 1) {
        if (tid < o) red[tid] += red[tid+o];
        __syncthreads();
    }
    float inv = 1.f / red[0];
    row[tid]     = e0 * inv;
    row[tid+256] = e1 * inv;
}

// ---------------- ctx = p @ v + band(p)·rel_v; write [B,C,T] -----------------
__global__ void k_ctx(const float* __restrict__ p, const float* __restrict__ v,
                      float* __restrict__ ctx, const float* __restrict__ rv_g) {
    __shared__ float Ps[64][33];
    __shared__ float Vs[64][33];
    __shared__ float rv[NREL][64];
    __shared__ float pb[64][NREL];
    __shared__ float Os[64][65];
    int tx = threadIdx.x, ty = threadIdx.y;
    int lid = ty*16 + tx;
    int t0 = blockIdx.x*64;
    int bh = blockIdx.y, b = bh >> 3, h = bh & 7;
    const float* vb = v + ((size_t)b*C + h*DK)*T;
    const float* prow = p + (size_t)bh*T*T;
    for (int e = lid; e < NREL*64; e += 256) rv[e/64][e%64] = rv_g[e];
    for (int e = lid; e < 64*NREL; e += 256) {
        int trow = e / NREL, dt = e % NREL;
        int t = t0 + trow, s = t + dt - W;
        pb[trow][dt] = (s >= 0 && s < T) ? prow[(size_t)t*T + s] : 0.f;
    }
    float acc[4][4] = {};
    for (int s0 = 0; s0 < T; s0 += 32) {
        for (int e = lid; e < 2048; e += 256) {
            int r = e >> 5, ss = e & 31;
            Ps[r][ss] = prow[(size_t)(t0+r)*T + s0 + ss];
        }
        for (int e = lid; e < 2048; e += 256) {
            int dd = e >> 5, ss = e & 31;
            Vs[dd][ss] = vb[(size_t)dd*T + s0 + ss];
        }
        __syncthreads();
#pragma unroll
        for (int kk = 0; kk < 32; kk++) {
            float pv[4], vv[4];
#pragma unroll
            for (int i = 0; i < 4; i++) pv[i] = Ps[ty*4+i][kk];
#pragma unroll
            for (int j = 0; j < 4; j++) vv[j] = Vs[tx+16*j][kk];
#pragma unroll
            for (int i = 0; i < 4; i++)
#pragma unroll
                for (int j = 0; j < 4; j++) acc[i][j] += pv[i]*vv[j];
        }
        __syncthreads();
    }
#pragma unroll
    for (int i = 0; i < 4; i++) {
        int trow = ty*4 + i;
#pragma unroll
        for (int j = 0; j < 4; j++) {
            int d = tx + 16*j;
            float r = acc[i][j];
#pragma unroll
            for (int dt = 0; dt < NREL; dt++) r += pb[trow][dt]*rv[dt][d];
            Os[d][trow] = r;
        }
    }
    __syncthreads();
    for (int e = lid; e < 4096; e += 256) {
        int dr = e >> 6, tc = e & 63;
        ctx[((size_t)b*C + h*DK + dr)*T + t0 + tc] = Os[dr][tc];
    }
}

// ---------------- channel LayerNorm of (h + y), in-place into h --------------
__global__ void k_ln(float* __restrict__ hbuf, const float* __restrict__ yv,
                     const float* __restrict__ g, const float* __restrict__ bb) {
    int tx = threadIdx.x, ty = threadIdx.y;
    int t = blockIdx.x*32 + tx, b = blockIdx.y;
    float s = 0.f, s2 = 0.f;
    for (int c = ty; c < C; c += 8) {
        size_t idx = ((size_t)b*C + c)*T + t;
        float v = hbuf[idx] + yv[idx];
        s += v; s2 += v*v;
    }
    __shared__ float rs[8][32], rs2[8][32];
    rs[ty][tx] = s; rs2[ty][tx] = s2;
    __syncthreads();
    if (ty == 0) {
        for (int j = 1; j < 8; j++) { s += rs[j][tx]; s2 += rs2[j][tx]; }
        float m = s / C;
        float var = s2 / C - m*m;
        rs[0][tx] = m;
        rs2[0][tx] = rsqrtf(var + 1e-5f);
    }
    __syncthreads();
    float m = rs[0][tx], r = rs2[0][tx];
    for (int c = ty; c < C; c += 8) {
        size_t idx = ((size_t)b*C + c)*T + t;
        float v = hbuf[idx] + yv[idx];
        hbuf[idx] = (v - m)*r*g[c] + bb[c];
    }
}

// ---------------- launch -----------------------------------------------------
extern "C" void kernel_launch(void* const* d_in, const int* in_sizes, int n_in,
                              void* d_out, int out_size) {
    const int*   x    = (const int*)d_in[0];
    const int*   xlen = (const int*)d_in[1];
    const float* emb  = (const float*)d_in[2];
    const float* Wq = (const float*)d_in[3],  *bq = (const float*)d_in[4];
    const float* Wk = (const float*)d_in[5],  *bk = (const float*)d_in[6];
    const float* Wv = (const float*)d_in[7],  *bv = (const float*)d_in[8];
    const float* Wo = (const float*)d_in[9],  *bo = (const float*)d_in[10];
    const float* rel_k = (const float*)d_in[11], *rel_v = (const float*)d_in[12];
    const float* ln1g = (const float*)d_in[13], *ln1b = (const float*)d_in[14];
    const float* ln2g = (const float*)d_in[15], *ln2b = (const float*)d_in[16];
    const float* w1 = (const float*)d_in[17], *b1 = (const float*)d_in[18];
    const float* w2 = (const float*)d_in[19], *b2 = (const float*)d_in[20];
    const float* pw = (const float*)d_in[21], *pbv = (const float*)d_in[22];
    float* out = (float*)d_out;
    size_t SZ = (size_t)B*C*T;

    float *ph,*pq,*pk,*pv,*pctx,*py,*pp,*pf;
    cudaGetSymbolAddress((void**)&ph,  g_h);
    cudaGetSymbolAddress((void**)&pq,  g_q);
    cudaGetSymbolAddress((void**)&pk,  g_k);
    cudaGetSymbolAddress((void**)&pv,  g_v);
    cudaGetSymbolAddress((void**)&pctx,g_ctx);
    cudaGetSymbolAddress((void**)&py,  g_y);
    cudaGetSymbolAddress((void**)&pp,  g_p);
    cudaGetSymbolAddress((void**)&pf,  g_f);

    dim3 blk(16,16);
    k_embed<<<dim3(T/32, B), dim3(32,8)>>>(x, xlen, emb, out, out + 4*SZ);

    for (int i = 0; i < LYR; i++) {
        k_maskh<<<(B*C*T)/256, 256>>>();
        k_gemm1x1<<<dim3(T/64, C/64, B), blk>>>(Wq + (size_t)i*C*C, bq + i*C, ph, pq, C, C, 0.125f, 0, 0);
        k_gemm1x1<<<dim3(T/64, C/64, B), blk>>>(Wk + (size_t)i*C*C, bk + i*C, ph, pk, C, C, 1.f, 0, 0);
        k_gemm1x1<<<dim3(T/64, C/64, B), blk>>>(Wv + (size_t)i*C*C, bv + i*C, ph, pv, C, C, 1.f, 0, 0);
        k_qk<<<dim3(T/64, T/64, B*H), blk>>>(pq, pk, pp);
        k_relband<<<dim3(T/32, H, B), dim3(32,8)>>>(pq, pp, rel_k + (size_t)i*NREL*DK);
        k_softmax<<<dim3(T, H, B), 256>>>(pp);
        k_ctx<<<dim3(T/64, B*H), blk>>>(pp, pv, pctx, rel_v + (size_t)i*NREL*DK);
        k_gemm1x1<<<dim3(T/64, C/64, B), blk>>>(Wo + (size_t)i*C*C, bo + i*C, pctx, py, C, C, 1.f, 0, 0);
        k_ln<<<dim3(T/32, B), dim3(32,8)>>>(ph, py, ln1g + i*C, ln1b + i*C);
        k_conv3<<<dim3(T/64, DFF/64, B), blk>>>(w1 + (size_t)i*DFF*C*KS, b1 + i*DFF, ph, pf, DFF, C, 1, 0);
        k_conv3<<<dim3(T/64, C/64, B), blk>>>(w2 + (size_t)i*C*DFF*KS, b2 + i*C, pf, py, C, DFF, 0, 1);
        k_ln<<<dim3(T/32, B), dim3(32,8)>>>(ph, py, ln2g + i*C, ln2b + i*C);
    }

    k_oen<<<(B*C*T)/256, 256>>>(out + SZ);
    k_gemm1x1<<<dim3(T/64, C/64, B), blk>>>(pw,                 pbv,     ph, out + 2*SZ, C, C, 1.f, 1, 1);
    k_gemm1x1<<<dim3(T/64, C/64, B), blk>>>(pw + (size_t)C*C,   pbv + C, ph, out + 3*SZ, C, C, 1.f, 1, 1);
}

// round 2
// speedup vs baseline: 1.7273x; 1.7273x over previous
#include <cuda_runtime.h>
#include <math.h>

#define B 8
#define T 512
#define C 512
#define DFF 2048
#define H 8
#define LYR 6
#define W 4
#define DK 64
#define NREL 9

typedef unsigned long long u64;

// ---------------- scratch ----------------------------------------------------
__device__ float g_h[B*C*T];
__device__ float g_q[B*C*T];
__device__ float g_k[B*C*T];
__device__ float g_v[B*C*T];
__device__ float g_ctx[B*C*T];
__device__ float g_y[B*C*T];
__device__ float g_p[(size_t)B*H*T*T];
__device__ float g_f[B*DFF*T];
__device__ float g_mask[B*T];
__device__ float g_w1t[C*3*DFF];   // transposed conv1 weights [ck][o]
__device__ float g_w2t[DFF*3*C];   // transposed conv2 weights [ck][o]

// ---------------- f32x2 helpers ----------------------------------------------
__device__ __forceinline__ u64 ffma2(u64 a, u64 b, u64 c) {
    u64 d; asm("fma.rn.f32x2 %0, %1, %2, %3;" : "=l"(d) : "l"(a), "l"(b), "l"(c));
    return d;
}
__device__ __forceinline__ u64 fpack2(float lo, float hi) {
    u64 d; asm("mov.b64 %0, {%1, %2};" : "=l"(d) : "f"(lo), "f"(hi));
    return d;
}
__device__ __forceinline__ float2 funpack2(u64 v) {
    float2 r; asm("mov.b64 {%0, %1}, %2;" : "=f"(r.x), "=f"(r.y) : "l"(v));
    return r;
}

// ---------------- embedding + mask -------------------------------------------
__global__ void k_embed(const int* __restrict__ x, const int* __restrict__ xlen,
                        const float* __restrict__ emb,
                        float* __restrict__ out_xemb, float* __restrict__ out_mask) {
    int b = blockIdx.y;
    int t = blockIdx.x * 32 + threadIdx.x;
    int xi = x[b*T + t];
    float mk = (t < xlen[b]) ? 1.f : 0.f;
    const float SQ = 22.627416997969522f;
    for (int c = threadIdx.y; c < C; c += 8) {
        float v = emb[xi*C + c] * SQ;
        out_xemb[((size_t)b*C + c)*T + t] = v;
        g_h[((size_t)b*C + c)*T + t] = v * mk;
    }
    if (threadIdx.y == 0) {
        g_mask[b*T + t] = mk;
        out_mask[b*T + t] = mk;
    }
}

__global__ void k_copy4(const float4* __restrict__ src, float4* __restrict__ dst) {
    int i = blockIdx.x * 256 + threadIdx.x;
    dst[i] = src[i];
}

// ---------------- weight transpose W[o][ck] -> Wt[ck][o] ----------------------
__global__ void k_transw(const float* __restrict__ Wm, float* __restrict__ Wt,
                         int O, int CK) {
    __shared__ float tile[32][33];
    int ck0 = blockIdx.x*32, o0 = blockIdx.y*32;
    int tx = threadIdx.x, ty = threadIdx.y;
#pragma unroll
    for (int i = 0; i < 4; i++)
        tile[ty + i*8][tx] = Wm[(size_t)(o0 + ty + i*8)*CK + ck0 + tx];
    __syncthreads();
#pragma unroll
    for (int i = 0; i < 4; i++)
        Wt[(size_t)(ck0 + ty + i*8)*O + o0 + tx] = tile[tx][ty + i*8];
}

// ---------------- conv1x1 GEMM (f32x2): Y[b,o,t] = W@X + bias ------------------
// tile: 128 o x 64 t, 256 threads, thread = 4 o x 8 t (4 pairs along t)
__global__ __launch_bounds__(256) void k_gemm1x1(
        const float* __restrict__ Wm, const float* __restrict__ bias,
        const float* __restrict__ X, float* __restrict__ Y,
        int O, int Cin, float scale, int maskOut) {
    __shared__ u64 Wd[128*35];
    __shared__ float Xs[32*68];
    int lid = threadIdx.x;
    int tx = lid & 7, ty = lid >> 3;
    int t0 = blockIdx.x*64, o0 = blockIdx.y*128, b = blockIdx.z;
    const float* Xb = X + (size_t)b*Cin*T;
    u64 acc[4][4];
#pragma unroll
    for (int i = 0; i < 4; i++)
#pragma unroll
        for (int j = 0; j < 4; j++) acc[i][j] = 0ull;

    for (int c0 = 0; c0 < Cin; c0 += 32) {
#pragma unroll
        for (int it = 0; it < 16; it++) {
            int e = lid + it*256; int r = e >> 5, cc = e & 31;
            float w = Wm[(size_t)(o0+r)*Cin + c0 + cc];
            Wd[r*35 + cc] = fpack2(w, w);
        }
#pragma unroll
        for (int it = 0; it < 8; it++) {
            int e = lid + it*256; int r = e >> 6, cc = e & 63;
            Xs[r*68 + cc] = Xb[(size_t)(c0+r)*T + t0 + cc];
        }
        __syncthreads();
#pragma unroll
        for (int kk = 0; kk < 32; kk++) {
            ulonglong2 xa = *(const ulonglong2*)&Xs[kk*68 + tx*8];
            ulonglong2 xb = *(const ulonglong2*)&Xs[kk*68 + tx*8 + 4];
#pragma unroll
            for (int i = 0; i < 4; i++) {
                u64 w = Wd[(ty*4+i)*35 + kk];
                acc[i][0] = ffma2(w, xa.x, acc[i][0]);
                acc[i][1] = ffma2(w, xa.y, acc[i][1]);
                acc[i][2] = ffma2(w, xb.x, acc[i][2]);
                acc[i][3] = ffma2(w, xb.y, acc[i][3]);
            }
        }
        __syncthreads();
    }
    float4 m0, m1;
    if (maskOut) {
        m0 = *(const float4*)&g_mask[b*T + t0 + tx*8];
        m1 = *(const float4*)&g_mask[b*T + t0 + tx*8 + 4];
    } else {
        m0 = make_float4(1.f,1.f,1.f,1.f); m1 = m0;
    }
#pragma unroll
    for (int i = 0; i < 4; i++) {
        int o = o0 + ty*4 + i;
        float bi = bias[o];
        float2 p0 = funpack2(acc[i][0]), p1 = funpack2(acc[i][1]);
        float2 p2 = funpack2(acc[i][2]), p3 = funpack2(acc[i][3]);
        float4 r0 = make_float4((p0.x+bi)*scale*m0.x, (p0.y+bi)*scale*m0.y,
                                (p1.x+bi)*scale*m0.z, (p1.y+bi)*scale*m0.w);
        float4 r1 = make_float4((p2.x+bi)*scale*m1.x, (p2.y+bi)*scale*m1.y,
                                (p3.x+bi)*scale*m1.z, (p3.y+bi)*scale*m1.w);
        *(float4*)&Y[((size_t)b*O + o)*T + t0 + tx*8] = r0;
        *(float4*)&Y[((size_t)b*O + o)*T + t0 + tx*8 + 4] = r1;
    }
}

// ---------------- conv1d K=3 (f32x2), weights pre-transposed [ck][o] ----------
// tile: 128 o x 64 t, 256 threads, thread = 8 o (4 pairs along o) x 4 t
extern __shared__ float cdyn[];
__global__ __launch_bounds__(256) void k_conv3(
        const float* __restrict__ Wt, const float* __restrict__ bias,
        const float* __restrict__ X, float* __restrict__ Y,
        int O, int Cin, int doRelu, int maskOut) {
    float* Wts = cdyn;                       // [96][128]
    float* Xs  = cdyn + 96*128;              // [32][68], col = t_off+1 (0..65)
    int lid = threadIdx.x;
    int tx = lid & 15, ty = lid >> 4;
    int t0 = blockIdx.x*64, o0 = blockIdx.y*128, b = blockIdx.z;
    const float* Xb = X + (size_t)b*Cin*T;
    u64 acc[4][4];
#pragma unroll
    for (int i = 0; i < 4; i++)
#pragma unroll
        for (int j = 0; j < 4; j++) acc[i][j] = 0ull;

    for (int c0 = 0; c0 < Cin; c0 += 32) {
#pragma unroll
        for (int it = 0; it < 48; it++) {
            int e = lid + it*256;
            Wts[e] = Wt[(size_t)(c0*3 + (e >> 7))*O + o0 + (e & 127)];
        }
        for (int e = lid; e < 32*66; e += 256) {
            int cc = e / 66, col = e % 66;
            int tg = t0 + col - 1;
            float v = 0.f;
            if (tg >= 0 && tg < T)
                v = Xb[(size_t)(c0+cc)*T + tg] * g_mask[b*T + tg];
            Xs[cc*68 + col] = v;
        }
        __syncthreads();
#pragma unroll 8
        for (int cc = 0; cc < 32; cc++) {
            float4 xa = *(const float4*)&Xs[cc*68 + tx*4];
            float2 xb = *(const float2*)&Xs[cc*68 + tx*4 + 4];
            u64 xd[6];
            xd[0] = fpack2(xa.x, xa.x); xd[1] = fpack2(xa.y, xa.y);
            xd[2] = fpack2(xa.z, xa.z); xd[3] = fpack2(xa.w, xa.w);
            xd[4] = fpack2(xb.x, xb.x); xd[5] = fpack2(xb.y, xb.y);
#pragma unroll
            for (int k = 0; k < 3; k++) {
                ulonglong2 wA = *(const ulonglong2*)&Wts[(cc*3+k)*128 + ty*8];
                ulonglong2 wB = *(const ulonglong2*)&Wts[(cc*3+k)*128 + ty*8 + 4];
#pragma unroll
                for (int tt = 0; tt < 4; tt++) {
                    u64 xx = xd[tt + k];
                    acc[0][tt] = ffma2(wA.x, xx, acc[0][tt]);
                    acc[1][tt] = ffma2(wA.y, xx, acc[1][tt]);
                    acc[2][tt] = ffma2(wB.x, xx, acc[2][tt]);
                    acc[3][tt] = ffma2(wB.y, xx, acc[3][tt]);
                }
            }
        }
        __syncthreads();
    }
    float4 mt = maskOut ? *(const float4*)&g_mask[b*T + t0 + tx*4]
                        : make_float4(1.f,1.f,1.f,1.f);
    int og = o0 + ty*8;
#pragma unroll
    for (int op = 0; op < 4; op++) {
        float2 bi = *(const float2*)&bias[og + op*2];
        float2 u0 = funpack2(acc[op][0]), u1 = funpack2(acc[op][1]);
        float2 u2 = funpack2(acc[op][2]), u3 = funpack2(acc[op][3]);
        float4 ve = make_float4(u0.x+bi.x, u1.x+bi.x, u2.x+bi.x, u3.x+bi.x);
        float4 vo = make_float4(u0.y+bi.y, u1.y+bi.y, u2.y+bi.y, u3.y+bi.y);
        if (doRelu) {
            ve.x = fmaxf(ve.x,0.f); ve.y = fmaxf(ve.y,0.f);
            ve.z = fmaxf(ve.z,0.f); ve.w = fmaxf(ve.w,0.f);
            vo.x = fmaxf(vo.x,0.f); vo.y = fmaxf(vo.y,0.f);
            vo.z = fmaxf(vo.z,0.f); vo.w = fmaxf(vo.w,0.f);
        }
        ve.x *= mt.x; ve.y *= mt.y; ve.z *= mt.z; ve.w *= mt.w;
        vo.x *= mt.x; vo.y *= mt.y; vo.z *= mt.z; vo.w *= mt.w;
        *(float4*)&Y[((size_t)b*O + og + op*2)*T + t0 + tx*4] = ve;
        *(float4*)&Y[((size_t)b*O + og + op*2 + 1)*T + t0 + tx*4] = vo;
    }
}

// ---------------- scores = q@k^T (f32x2) --------------------------------------
// tile: 128 t x 64 s, 256 threads, thread = 4 t x 8 s (4 pairs along s)
__global__ __launch_bounds__(256) void k_qk(const float* __restrict__ q,
                                            const float* __restrict__ k,
                                            float* __restrict__ p) {
    __shared__ u64 Qd[128*35];
    __shared__ float Ks[32*68];
    int lid = threadIdx.x;
    int tx = lid & 7, ty = lid >> 3;
    int s0 = blockIdx.x*64, t0 = blockIdx.y*128;
    int bh = blockIdx.z, b = bh >> 3, h = bh & 7;
    const float* qb = q + ((size_t)b*C + h*DK)*T;
    const float* kb = k + ((size_t)b*C + h*DK)*T;
    u64 acc[4][4];
#pragma unroll
    for (int i = 0; i < 4; i++)
#pragma unroll
        for (int j = 0; j < 4; j++) acc[i][j] = 0ull;

    for (int d0 = 0; d0 < DK; d0 += 32) {
#pragma unroll
        for (int it = 0; it < 16; it++) {
            int e = lid + it*256; int dd = e >> 7, tt = e & 127;
            float v = qb[(size_t)(d0+dd)*T + t0 + tt];
            Qd[tt*35 + dd] = fpack2(v, v);
        }
#pragma unroll
        for (int it = 0; it < 8; it++) {
            int e = lid + it*256; int r = e >> 6, cc = e & 63;
            Ks[r*68 + cc] = kb[(size_t)(d0+r)*T + s0 + cc];
        }
        __syncthreads();
#pragma unroll
        for (int kk = 0; kk < 32; kk++) {
            ulonglong2 xa = *(const ulonglong2*)&Ks[kk*68 + tx*8];
            ulonglong2 xb = *(const ulonglong2*)&Ks[kk*68 + tx*8 + 4];
#pragma unroll
            for (int i = 0; i < 4; i++) {
                u64 w = Qd[(ty*4+i)*35 + kk];
                acc[i][0] = ffma2(w, xa.x, acc[i][0]);
                acc[i][1] = ffma2(w, xa.y, acc[i][1]);
                acc[i][2] = ffma2(w, xb.x, acc[i][2]);
                acc[i][3] = ffma2(w, xb.y, acc[i][3]);
            }
        }
        __syncthreads();
    }
#pragma unroll
    for (int i = 0; i < 4; i++) {
        int t = t0 + ty*4 + i;
        float2 p0 = funpack2(acc[i][0]), p1 = funpack2(acc[i][1]);
        float2 p2 = funpack2(acc[i][2]), p3 = funpack2(acc[i][3]);
        float4 r0 = make_float4(p0.x, p0.y, p1.x, p1.y);
        float4 r1 = make_float4(p2.x, p2.y, p3.x, p3.y);
        *(float4*)&p[((size_t)bh*T + t)*T + s0 + tx*8] = r0;
        *(float4*)&p[((size_t)bh*T + t)*T + s0 + tx*8 + 4] = r1;
    }
}

// ---------------- relative band add ------------------------------------------
__global__ void k_relband(const float* __restrict__ q, float* __restrict__ p,
                          const float* __restrict__ rk) {
    __shared__ float qs[32][65];
    __shared__ float rks[NREL][64];
    int b = blockIdx.z, h = blockIdx.y, t0 = blockIdx.x*32;
    int lid = threadIdx.y*32 + threadIdx.x;
    const float* qb = q + ((size_t)b*C + h*DK)*T;
    for (int e = lid; e < 2048; e += 256) {
        int d = e >> 5, tt = e & 31;
        qs[tt][d] = qb[(size_t)d*T + t0 + tt];
    }
    for (int e = lid; e < NREL*64; e += 256) rks[e/64][e%64] = rk[e];
    __syncthreads();
    for (int w = lid; w < 32*NREL; w += 256) {
        int trow = w / NREL, dt = w % NREL;
        int t = t0 + trow, s = t + dt - W;
        if (s >= 0 && s < T) {
            float dot = 0.f;
#pragma unroll
            for (int d = 0; d < 64; d++) dot += qs[trow][d]*rks[dt][d];
            p[(((size_t)(b*H + h))*T + t)*T + s] += dot;
        }
    }
}

// ---------------- masked softmax ----------------------------------------------
__global__ void k_softmax(float* __restrict__ p) {
    int t = blockIdx.x, h = blockIdx.y, b = blockIdx.z;
    float* row = p + (((size_t)(b*H + h))*T + t)*T;
    int tid = threadIdx.x;
    float mt = g_mask[b*T + t];
    float v0 = row[tid], v1 = row[tid+256];
    if (mt * g_mask[b*T + tid]       == 0.f) v0 = -1e4f;
    if (mt * g_mask[b*T + tid + 256] == 0.f) v1 = -1e4f;
    float mx = fmaxf(v0, v1);
#pragma unroll
    for (int o = 16; o; o >>= 1) mx = fmaxf(mx, __shfl_xor_sync(0xffffffffu, mx, o));
    __shared__ float sm[8], ss[8];
    int wid = tid >> 5, lane = tid & 31;
    if (!lane) sm[wid] = mx;
    __syncthreads();
    mx = sm[0];
#pragma unroll
    for (int i = 1; i < 8; i++) mx = fmaxf(mx, sm[i]);
    float e0 = expf(v0 - mx), e1 = expf(v1 - mx);
    float s = e0 + e1;
#pragma unroll
    for (int o = 16; o; o >>= 1) s += __shfl_xor_sync(0xffffffffu, s, o);
    if (!lane) ss[wid] = s;
    __syncthreads();
    s = ss[0];
#pragma unroll
    for (int i = 1; i < 8; i++) s += ss[i];
    float inv = 1.f / s;
    row[tid]     = e0 * inv;
    row[tid+256] = e1 * inv;
}

// ---------------- ctx = p@v + band(p)@rel_v (f32x2) ----------------------------
// tile: 64 d x 128 t per bh-block, 256 threads, thread = 4 d x 8 t (4 pairs)
__global__ __launch_bounds__(256) void k_ctx(const float* __restrict__ p,
                                             const float* __restrict__ v,
                                             float* __restrict__ ctx,
                                             const float* __restrict__ rv_g) {
    __shared__ u64 Vd[64*35];
    __shared__ float Ps[32*132];   // [s][t]
    __shared__ u64 pbs[NREL*64];   // band probs, pairs over t
    __shared__ u64 rvd[NREL*64];   // rel_v duplicated
    int lid = threadIdx.x;
    int tx = lid & 15, ty = lid >> 4;
    int t0 = blockIdx.x*128;
    int bh = blockIdx.y, b = bh >> 3, h = bh & 7;
    const float* vb = v + ((size_t)b*C + h*DK)*T;
    const float* prow = p + (size_t)bh*T*T;

    for (int e = lid; e < NREL*64; e += 256) rvd[e] = fpack2(rv_g[e], rv_g[e]);
    for (int e = lid; e < NREL*64; e += 256) {
        int dt = e >> 6, tp = e & 63;
        int te = t0 + tp*2;
        int se = te + dt - W, so = se + 1;
        float a = (se >= 0 && se < T) ? prow[(size_t)te*T + se] : 0.f;
        float c = (so >= 0 && so < T) ? prow[(size_t)(te+1)*T + so] : 0.f;
        pbs[e] = fpack2(a, c);
    }

    u64 acc[4][4];
#pragma unroll
    for (int i = 0; i < 4; i++)
#pragma unroll
        for (int j = 0; j < 4; j++) acc[i][j] = 0ull;

    for (int s0 = 0; s0 < T; s0 += 32) {
#pragma unroll
        for (int it = 0; it < 8; it++) {
            int e = lid + it*256; int dd = e >> 5, sscol = e & 31;
            float val = vb[(size_t)dd*T + s0 + sscol];
            Vd[dd*35 + sscol] = fpack2(val, val);
        }
#pragma unroll
        for (int it = 0; it < 4; it++) {
            int u = lid + it*256; int sg = u & 7, tt = u >> 3;
            float4 pv = *(const float4*)&prow[(size_t)(t0+tt)*T + s0 + sg*4];
            Ps[(sg*4+0)*132 + tt] = pv.x;
            Ps[(sg*4+1)*132 + tt] = pv.y;
            Ps[(sg*4+2)*132 + tt] = pv.z;
            Ps[(sg*4+3)*132 + tt] = pv.w;
        }
        __syncthreads();
#pragma unroll
        for (int kk = 0; kk < 32; kk++) {
            ulonglong2 xa = *(const ulonglong2*)&Ps[kk*132 + tx*8];
            ulonglong2 xb = *(const ulonglong2*)&Ps[kk*132 + tx*8 + 4];
#pragma unroll
            for (int i = 0; i < 4; i++) {
                u64 w = Vd[(ty*4+i)*35 + kk];
                acc[i][0] = ffma2(w, xa.x, acc[i][0]);
                acc[i][1] = ffma2(w, xa.y, acc[i][1]);
                acc[i][2] = ffma2(w, xb.x, acc[i][2]);
                acc[i][3] = ffma2(w, xb.y, acc[i][3]);
            }
        }
        __syncthreads();
    }
    // band epilogue
#pragma unroll
    for (int dt = 0; dt < NREL; dt++) {
#pragma unroll
        for (int i = 0; i < 4; i++) {
            u64 w = rvd[dt*64 + ty*4 + i];
#pragma unroll
            for (int jp = 0; jp < 4; jp++)
                acc[i][jp] = ffma2(w, pbs[dt*64 + tx*4 + jp], acc[i][jp]);
        }
    }
#pragma unroll
    for (int i = 0; i < 4; i++) {
        float2 p0 = funpack2(acc[i][0]), p1 = funpack2(acc[i][1]);
        float2 p2 = funpack2(acc[i][2]), p3 = funpack2(acc[i][3]);
        float4 r0 = make_float4(p0.x, p0.y, p1.x, p1.y);
        float4 r1 = make_float4(p2.x, p2.y, p3.x, p3.y);
        size_t base = ((size_t)b*C + h*DK + ty*4 + i)*T + t0 + tx*8;
        *(float4*)&ctx[base]     = r0;
        *(float4*)&ctx[base + 4] = r1;
    }
}

// ---------------- channel LayerNorm -------------------------------------------
__global__ void k_ln(float* __restrict__ hbuf, const float* __restrict__ yv,
                     const float* __restrict__ g, const float* __restrict__ bb,
                     int maskOut) {
    int tx = threadIdx.x, ty = threadIdx.y;
    int t = blockIdx.x*32 + tx, b = blockIdx.y;
    float s = 0.f, s2 = 0.f;
    for (int c = ty; c < C; c += 8) {
        size_t idx = ((size_t)b*C + c)*T + t;
        float v = hbuf[idx] + yv[idx];
        s += v; s2 += v*v;
    }
    __shared__ float rs[8][32], rs2[8][32];
    rs[ty][tx] = s; rs2[ty][tx] = s2;
    __syncthreads();
    if (ty == 0) {
        for (int j = 1; j < 8; j++) { s += rs[j][tx]; s2 += rs2[j][tx]; }
        float m = s / C;
        float var = s2 / C - m*m;
        rs[0][tx] = m;
        rs2[0][tx] = rsqrtf(var + 1e-5f);
    }
    __syncthreads();
    float m = rs[0][tx], r = rs2[0][tx];
    float mk = maskOut ? g_mask[b*T + t] : 1.f;
    for (int c = ty; c < C; c += 8) {
        size_t idx = ((size_t)b*C + c)*T + t;
        float v = hbuf[idx] + yv[idx];
        hbuf[idx] = ((v - m)*r*g[c] + bb[c]) * mk;
    }
}

// ---------------- launch -------------------------------------------------------
extern "C" void kernel_launch(void* const* d_in, const int* in_sizes, int n_in,
                              void* d_out, int out_size) {
    const int*   x    = (const int*)d_in[0];
    const int*   xlen = (const int*)d_in[1];
    const float* emb  = (const float*)d_in[2];
    const float* Wq = (const float*)d_in[3],  *bq = (const float*)d_in[4];
    const float* Wk = (const float*)d_in[5],  *bk = (const float*)d_in[6];
    const float* Wv = (const float*)d_in[7],  *bv = (const float*)d_in[8];
    const float* Wo = (const float*)d_in[9],  *bo = (const float*)d_in[10];
    const float* rel_k = (const float*)d_in[11], *rel_v = (const float*)d_in[12];
    const float* ln1g = (const float*)d_in[13], *ln1b = (const float*)d_in[14];
    const float* ln2g = (const float*)d_in[15], *ln2b = (const float*)d_in[16];
    const float* w1 = (const float*)d_in[17], *b1 = (const float*)d_in[18];
    const float* w2 = (const float*)d_in[19], *b2 = (const float*)d_in[20];
    const float* pw = (const float*)d_in[21], *pbv = (const float*)d_in[22];
    float* out = (float*)d_out;
    size_t SZ = (size_t)B*C*T;

    float *ph,*pq,*pk,*pv,*pctx,*py,*pp,*pf,*pw1t,*pw2t;
    cudaGetSymbolAddress((void**)&ph,  g_h);
    cudaGetSymbolAddress((void**)&pq,  g_q);
    cudaGetSymbolAddress((void**)&pk,  g_k);
    cudaGetSymbolAddress((void**)&pv,  g_v);
    cudaGetSymbolAddress((void**)&pctx,g_ctx);
    cudaGetSymbolAddress((void**)&py,  g_y);
    cudaGetSymbolAddress((void**)&pp,  g_p);
    cudaGetSymbolAddress((void**)&pf,  g_f);
    cudaGetSymbolAddress((void**)&pw1t, g_w1t);
    cudaGetSymbolAddress((void**)&pw2t, g_w2t);

    static int smem_set = 0;
    int conv_smem = (96*128 + 32*68) * 4;
    if (!smem_set) {
        cudaFuncSetAttribute(k_conv3, cudaFuncAttributeMaxDynamicSharedMemorySize, conv_smem);
        smem_set = 1;
    }

    k_embed<<<dim3(T/32, B), dim3(32,8)>>>(x, xlen, emb, out, out + 4*SZ);

    for (int i = 0; i < LYR; i++) {
        k_gemm1x1<<<dim3(T/64, C/128, B), 256>>>(Wq + (size_t)i*C*C, bq + i*C, ph, pq, C, C, 0.125f, 0);
        k_gemm1x1<<<dim3(T/64, C/128, B), 256>>>(Wk + (size_t)i*C*C, bk + i*C, ph, pk, C, C, 1.f, 0);
        k_gemm1x1<<<dim3(T/64, C/128, B), 256>>>(Wv + (size_t)i*C*C, bv + i*C, ph, pv, C, C, 1.f, 0);
        k_qk<<<dim3(T/64, T/128, B*H), 256>>>(pq, pk, pp);
        k_relband<<<dim3(T/32, H, B), dim3(32,8)>>>(pq, pp, rel_k + (size_t)i*NREL*DK);
        k_softmax<<<dim3(T, H, B), 256>>>(pp);
        k_ctx<<<dim3(T/128, B*H), 256>>>(pp, pv, pctx, rel_v + (size_t)i*NREL*DK);
        k_gemm1x1<<<dim3(T/64, C/128, B), 256>>>(Wo + (size_t)i*C*C, bo + i*C, pctx, py, C, C, 1.f, 0);
        k_ln<<<dim3(T/32, B), dim3(32,8)>>>(ph, py, ln1g + i*C, ln1b + i*C, 0);
        k_transw<<<dim3((C*3)/32, DFF/32), dim3(32,8)>>>(w1 + (size_t)i*DFF*C*3, pw1t, DFF, C*3);
        k_conv3<<<dim3(T/64, DFF/128, B), 256, conv_smem>>>(pw1t, b1 + i*DFF, ph, pf, DFF, C, 1, 0);
        k_transw<<<dim3((DFF*3)/32, C/32), dim3(32,8)>>>(w2 + (size_t)i*C*DFF*3, pw2t, C, DFF*3);
        k_conv3<<<dim3(T/64, C/128, B), 256, conv_smem>>>(pw2t, b2 + i*C, pf, py, C, DFF, 0, 1);
        k_ln<<<dim3(T/32, B), dim3(32,8)>>>(ph, py, ln2g + i*C, ln2b + i*C, 1);
    }

    k_copy4<<<(B*C*T)/1024, 256>>>((const float4*)ph, (float4*)(out + SZ));
    k_gemm1x1<<<dim3(T/64, C/128, B), 256>>>(pw,               pbv,     ph, out + 2*SZ, C, C, 1.f, 1);
    k_gemm1x1<<<dim3(T/64, C/128, B), 256>>>(pw + (size_t)C*C, pbv + C, ph, out + 3*SZ, C, C, 1.f, 1);
}

// round 3
// speedup vs baseline: 1.9555x; 1.1321x over previous
#include <cuda_runtime.h>
#include <math.h>

#define B 8
#define T 512
#define C 512
#define DFF 2048
#define H 8
#define LYR 6
#define W 4
#define DK 64
#define NREL 9

typedef unsigned long long u64;
typedef unsigned int u32;

// ---------------- scratch ----------------------------------------------------
__device__ float g_h[B*C*T];
__device__ float g_q[B*C*T];
__device__ float g_k[B*C*T];
__device__ float g_v[B*C*T];
__device__ float g_ctx[B*C*T];
__device__ float g_y[B*C*T];
__device__ float g_p[(size_t)B*H*T*T];
__device__ float g_f[B*DFF*T];
__device__ float g_mask[B*T];
__device__ float g_wt4[4*C*C];      // transposed Wq,Wk,Wv,Wo for one layer
__device__ float g_w1t[C*3*DFF];    // transposed conv1 weights [ck][o]
__device__ float g_w2t[DFF*3*C];    // transposed conv2 weights [ck][o]
__device__ float g_pwt[C*2*C];      // transposed proj weights [c][o], ld=1024

// ---------------- helpers ------------------------------------------------------
__device__ __forceinline__ u64 ffma2(u64 a, u64 b, u64 c) {
    u64 d; asm("fma.rn.f32x2 %0, %1, %2, %3;" : "=l"(d) : "l"(a), "l"(b), "l"(c));
    return d;
}
__device__ __forceinline__ u64 fpack2(float lo, float hi) {
    u64 d; asm("mov.b64 %0, {%1, %2};" : "=l"(d) : "f"(lo), "f"(hi));
    return d;
}
__device__ __forceinline__ float2 funpack2(u64 v) {
    float2 r; asm("mov.b64 {%0, %1}, %2;" : "=f"(r.x), "=f"(r.y) : "l"(v));
    return r;
}
__device__ __forceinline__ u32 tf32u(float x) {
    u32 r; asm("cvt.rna.tf32.f32 %0, %1;" : "=r"(r) : "f"(x)); return r;
}
__device__ __forceinline__ void mma8(float* d, u32 a0, u32 a1, u32 a2, u32 a3,
                                     u32 b0, u32 b1) {
    asm("mma.sync.aligned.m16n8k8.row.col.f32.tf32.tf32.f32 "
        "{%0,%1,%2,%3}, {%4,%5,%6,%7}, {%8,%9}, {%0,%1,%2,%3};"
        : "+f"(d[0]), "+f"(d[1]), "+f"(d[2]), "+f"(d[3])
        : "r"(a0), "r"(a1), "r"(a2), "r"(a3), "r"(b0), "r"(b1));
}
__device__ __forceinline__ u32 fbits(float x) { return __float_as_uint(x); }

// ---------------- embedding + mask -------------------------------------------
__global__ void k_embed(const int* __restrict__ x, const int* __restrict__ xlen,
                        const float* __restrict__ emb,
                        float* __restrict__ out_xemb, float* __restrict__ out_mask) {
    int b = blockIdx.y;
    int t = blockIdx.x * 32 + threadIdx.x;
    int xi = x[b*T + t];
    float mk = (t < xlen[b]) ? 1.f : 0.f;
    const float SQ = 22.627416997969522f;
    for (int c = threadIdx.y; c < C; c += 8) {
        float v = emb[xi*C + c] * SQ;
        out_xemb[((size_t)b*C + c)*T + t] = v;
        g_h[((size_t)b*C + c)*T + t] = v * mk;
    }
    if (threadIdx.y == 0) {
        g_mask[b*T + t] = mk;
        out_mask[b*T + t] = mk;
    }
}

__global__ void k_copy4(const float4* __restrict__ src, float4* __restrict__ dst) {
    int i = blockIdx.x * 256 + threadIdx.x;
    dst[i] = src[i];
}

// ---------------- weight transpose W[o][ck] -> Wt[ck][o] ----------------------
__global__ void k_transw(const float* __restrict__ Wm, float* __restrict__ Wt,
                         int O, int CK) {
    __shared__ float tile[32][33];
    int ck0 = blockIdx.x*32, o0 = blockIdx.y*32;
    int tx = threadIdx.x, ty = threadIdx.y;
#pragma unroll
    for (int i = 0; i < 4; i++)
        tile[ty + i*8][tx] = Wm[(size_t)(o0 + ty + i*8)*CK + ck0 + tx];
    __syncthreads();
#pragma unroll
    for (int i = 0; i < 4; i++)
        Wt[(size_t)(ck0 + ty + i*8)*O + o0 + tx] = tile[tx][ty + i*8];
}

// ---------------- unified tf32 mma GEMM/conv -----------------------------------
// Y[b,o,t0+tc] = sum_{c,kp} Wt[(c*KK+kp)][o] * Xin[b][c][t0+tc+kp-pad] (+bias,...)
// block: 128 o x 128 t; 8 warps as 4(M) x 2(N); warp: 32 o x 64 t
template<int KK>
__global__ __launch_bounds__(256) void k_mma(
        const float* __restrict__ Wt, int ldW,
        const float* __restrict__ bias,
        const float* __restrict__ X, float* __restrict__ Y,
        int Ostr, int Cin, float scale, int relu, int maskIn, int maskOut) {
    extern __shared__ float smdyn[];
    const int BC = 136;
    const int NCOL = 128 + KK - 1;
    const int PAD = (KK - 1) / 2;
    float* Ah = smdyn;
    float* Al = Ah + KK*32*BC;
    float* Bh = Al + KK*32*BC;
    float* Bl = Bh + 32*BC;

    int tid = threadIdx.x;
    int warp = tid >> 5, lane = tid & 31;
    int g = lane >> 2, tq = lane & 3;
    int wm = warp & 3, wn = warp >> 2;
    int t0 = blockIdx.x * 128, o0 = blockIdx.y * 128, b = blockIdx.z;
    const float* Xb = X + (size_t)b * Cin * T;
    const float* mrow = g_mask + b*T;

    float acc[2][8][4];
#pragma unroll
    for (int mi = 0; mi < 2; mi++)
#pragma unroll
        for (int ni = 0; ni < 8; ni++)
#pragma unroll
            for (int q = 0; q < 4; q++) acc[mi][ni][q] = 0.f;

    for (int c0 = 0; c0 < Cin; c0 += 32) {
        // load A tile (32*KK rows of 128 floats) with tf32 hi/lo split
#pragma unroll
        for (int it = 0; it < 4*KK; it++) {
            int e = tid + it*256;
            int rr = e >> 5, oc = (e & 31) << 2;
            float4 w4 = *(const float4*)&Wt[(size_t)(c0*KK + rr)*ldW + o0 + oc];
            int kp, cc;
            if (KK == 1) { kp = 0; cc = rr; } else { kp = rr % KK; cc = rr / KK; }
            float* dh = &Ah[(kp*32 + cc)*BC + oc];
            float* dl = &Al[(kp*32 + cc)*BC + oc];
            float h0 = __uint_as_float(tf32u(w4.x));
            float h1 = __uint_as_float(tf32u(w4.y));
            float h2 = __uint_as_float(tf32u(w4.z));
            float h3 = __uint_as_float(tf32u(w4.w));
            *(float4*)dh = make_float4(h0, h1, h2, h3);
            *(float4*)dl = make_float4(
                __uint_as_float(tf32u(w4.x - h0)), __uint_as_float(tf32u(w4.y - h1)),
                __uint_as_float(tf32u(w4.z - h2)), __uint_as_float(tf32u(w4.w - h3)));
        }
        // load B tile 32 x NCOL
        for (int e = tid; e < 32*NCOL; e += 256) {
            int cc = e / NCOL, j = e % NCOL;
            int t = t0 + j - PAD;
            float v = 0.f;
            if (t >= 0 && t < T) {
                v = Xb[(size_t)(c0+cc)*T + t];
                if (maskIn) v *= mrow[t];
            }
            float hv = __uint_as_float(tf32u(v));
            Bh[cc*BC + j] = hv;
            Bl[cc*BC + j] = __uint_as_float(tf32u(v - hv));
        }
        __syncthreads();
#pragma unroll
        for (int kp = 0; kp < KK; kp++) {
            const float* Abh = Ah + kp*32*BC;
            const float* Abl = Al + kp*32*BC;
#pragma unroll
            for (int k8 = 0; k8 < 4; k8++) {
                int r0 = k8*8 + tq, r1 = r0 + 4;
                u32 ah[2][4], al[2][4];
#pragma unroll
                for (int mi = 0; mi < 2; mi++) {
                    int ob = wm*32 + mi*16 + g;
                    ah[mi][0] = fbits(Abh[r0*BC + ob]);
                    ah[mi][1] = fbits(Abh[r0*BC + ob + 8]);
                    ah[mi][2] = fbits(Abh[r1*BC + ob]);
                    ah[mi][3] = fbits(Abh[r1*BC + ob + 8]);
                    al[mi][0] = fbits(Abl[r0*BC + ob]);
                    al[mi][1] = fbits(Abl[r0*BC + ob + 8]);
                    al[mi][2] = fbits(Abl[r1*BC + ob]);
                    al[mi][3] = fbits(Abl[r1*BC + ob + 8]);
                }
#pragma unroll
                for (int ni = 0; ni < 8; ni++) {
                    int jb = wn*64 + ni*8 + g + kp;
                    u32 bh0 = fbits(Bh[r0*BC + jb]);
                    u32 bh1 = fbits(Bh[r1*BC + jb]);
                    u32 bl0 = fbits(Bl[r0*BC + jb]);
                    u32 bl1 = fbits(Bl[r1*BC + jb]);
#pragma unroll
                    for (int mi = 0; mi < 2; mi++) {
                        mma8(acc[mi][ni], al[mi][0], al[mi][1], al[mi][2], al[mi][3], bh0, bh1);
                        mma8(acc[mi][ni], ah[mi][0], ah[mi][1], ah[mi][2], ah[mi][3], bl0, bl1);
                        mma8(acc[mi][ni], ah[mi][0], ah[mi][1], ah[mi][2], ah[mi][3], bh0, bh1);
                    }
                }
            }
        }
        __syncthreads();
    }
    // epilogue
#pragma unroll
    for (int mi = 0; mi < 2; mi++) {
#pragma unroll
        for (int half = 0; half < 2; half++) {
            int o = o0 + wm*32 + mi*16 + g + half*8;
            float bi = bias[o];
#pragma unroll
            for (int ni = 0; ni < 8; ni++) {
                int t = t0 + wn*64 + ni*8 + 2*tq;
                float v0 = (acc[mi][ni][half*2 + 0] + bi) * scale;
                float v1 = (acc[mi][ni][half*2 + 1] + bi) * scale;
                if (relu) { v0 = fmaxf(v0, 0.f); v1 = fmaxf(v1, 0.f); }
                if (maskOut) { v0 *= mrow[t]; v1 *= mrow[t+1]; }
                *(float2*)&Y[((size_t)b*Ostr + o)*T + t] = make_float2(v0, v1);
            }
        }
    }
}

// ---------------- scores = q@k^T (f32x2) --------------------------------------
__global__ __launch_bounds__(256) void k_qk(const float* __restrict__ q,
                                            const float* __restrict__ k,
                                            float* __restrict__ p) {
    __shared__ u64 Qd[128*35];
    __shared__ float Ks[32*68];
    int lid = threadIdx.x;
    int tx = lid & 7, ty = lid >> 3;
    int s0 = blockIdx.x*64, t0 = blockIdx.y*128;
    int bh = blockIdx.z, b = bh >> 3, h = bh & 7;
    const float* qb = q + ((size_t)b*C + h*DK)*T;
    const float* kb = k + ((size_t)b*C + h*DK)*T;
    u64 acc[4][4];
#pragma unroll
    for (int i = 0; i < 4; i++)
#pragma unroll
        for (int j = 0; j < 4; j++) acc[i][j] = 0ull;

    for (int d0 = 0; d0 < DK; d0 += 32) {
#pragma unroll
        for (int it = 0; it < 16; it++) {
            int e = lid + it*256; int dd = e >> 7, tt = e & 127;
            float v = qb[(size_t)(d0+dd)*T + t0 + tt];
            Qd[tt*35 + dd] = fpack2(v, v);
        }
#pragma unroll
        for (int it = 0; it < 8; it++) {
            int e = lid + it*256; int r = e >> 6, cc = e & 63;
            Ks[r*68 + cc] = kb[(size_t)(d0+r)*T + s0 + cc];
        }
        __syncthreads();
#pragma unroll
        for (int kk = 0; kk < 32; kk++) {
            ulonglong2 xa = *(const ulonglong2*)&Ks[kk*68 + tx*8];
            ulonglong2 xb = *(const ulonglong2*)&Ks[kk*68 + tx*8 + 4];
#pragma unroll
            for (int i = 0; i < 4; i++) {
                u64 w = Qd[(ty*4+i)*35 + kk];
                acc[i][0] = ffma2(w, xa.x, acc[i][0]);
                acc[i][1] = ffma2(w, xa.y, acc[i][1]);
                acc[i][2] = ffma2(w, xb.x, acc[i][2]);
                acc[i][3] = ffma2(w, xb.y, acc[i][3]);
            }
        }
        __syncthreads();
    }
#pragma unroll
    for (int i = 0; i < 4; i++) {
        int t = t0 + ty*4 + i;
        float2 p0 = funpack2(acc[i][0]), p1 = funpack2(acc[i][1]);
        float2 p2 = funpack2(acc[i][2]), p3 = funpack2(acc[i][3]);
        float4 r0 = make_float4(p0.x, p0.y, p1.x, p1.y);
        float4 r1 = make_float4(p2.x, p2.y, p3.x, p3.y);
        *(float4*)&p[((size_t)bh*T + t)*T + s0 + tx*8] = r0;
        *(float4*)&p[((size_t)bh*T + t)*T + s0 + tx*8 + 4] = r1;
    }
}

// ---------------- relative band add ------------------------------------------
__global__ void k_relband(const float* __restrict__ q, float* __restrict__ p,
                          const float* __restrict__ rk) {
    __shared__ float qs[32][65];
    __shared__ float rks[NREL][64];
    int b = blockIdx.z, h = blockIdx.y, t0 = blockIdx.x*32;
    int lid = threadIdx.y*32 + threadIdx.x;
    const float* qb = q + ((size_t)b*C + h*DK)*T;
    for (int e = lid; e < 2048; e += 256) {
        int d = e >> 5, tt = e & 31;
        qs[tt][d] = qb[(size_t)d*T + t0 + tt];
    }
    for (int e = lid; e < NREL*64; e += 256) rks[e/64][e%64] = rk[e];
    __syncthreads();
    for (int w = lid; w < 32*NREL; w += 256) {
        int trow = w / NREL, dt = w % NREL;
        int t = t0 + trow, s = t + dt - W;
        if (s >= 0 && s < T) {
            float dot = 0.f;
#pragma unroll
            for (int d = 0; d < 64; d++) dot += qs[trow][d]*rks[dt][d];
            p[(((size_t)(b*H + h))*T + t)*T + s] += dot;
        }
    }
}

// ---------------- masked softmax ----------------------------------------------
__global__ void k_softmax(float* __restrict__ p) {
    int t = blockIdx.x, h = blockIdx.y, b = blockIdx.z;
    float* row = p + (((size_t)(b*H + h))*T + t)*T;
    int tid = threadIdx.x;
    float mt = g_mask[b*T + t];
    float v0 = row[tid], v1 = row[tid+256];
    if (mt * g_mask[b*T + tid]       == 0.f) v0 = -1e4f;
    if (mt * g_mask[b*T + tid + 256] == 0.f) v1 = -1e4f;
    float mx = fmaxf(v0, v1);
#pragma unroll
    for (int o = 16; o; o >>= 1) mx = fmaxf(mx, __shfl_xor_sync(0xffffffffu, mx, o));
    __shared__ float sm[8], ss[8];
    int wid = tid >> 5, lane = tid & 31;
    if (!lane) sm[wid] = mx;
    __syncthreads();
    mx = sm[0];
#pragma unroll
    for (int i = 1; i < 8; i++) mx = fmaxf(mx, sm[i]);
    float e0 = expf(v0 - mx), e1 = expf(v1 - mx);
    float s = e0 + e1;
#pragma unroll
    for (int o = 16; o; o >>= 1) s += __shfl_xor_sync(0xffffffffu, s, o);
    if (!lane) ss[wid] = s;
    __syncthreads();
    s = ss[0];
#pragma unroll
    for (int i = 1; i < 8; i++) s += ss[i];
    float inv = 1.f / s;
    row[tid]     = e0 * inv;
    row[tid+256] = e1 * inv;
}

// ---------------- ctx = p@v + band(p)@rel_v (f32x2) ----------------------------
__global__ __launch_bounds__(256) void k_ctx(const float* __restrict__ p,
                                             const float* __restrict__ v,
                                             float* __restrict__ ctx,
                                             const float* __restrict__ rv_g) {
    __shared__ u64 Vd[64*35];
    __shared__ float Ps[32*132];
    __shared__ u64 pbs[NREL*64];
    __shared__ u64 rvd[NREL*64];
    int lid = threadIdx.x;
    int tx = lid & 15, ty = lid >> 4;
    int t0 = blockIdx.x*128;
    int bh = blockIdx.y, b = bh >> 3, h = bh & 7;
    const float* vb = v + ((size_t)b*C + h*DK)*T;
    const float* prow = p + (size_t)bh*T*T;

    for (int e = lid; e < NREL*64; e += 256) rvd[e] = fpack2(rv_g[e], rv_g[e]);
    for (int e = lid; e < NREL*64; e += 256) {
        int dt = e >> 6, tp = e & 63;
        int te = t0 + tp*2;
        int se = te + dt - W, so = se + 1;
        float a = (se >= 0 && se < T) ? prow[(size_t)te*T + se] : 0.f;
        float c = (so >= 0 && so < T) ? prow[(size_t)(te+1)*T + so] : 0.f;
        pbs[e] = fpack2(a, c);
    }

    u64 acc[4][4];
#pragma unroll
    for (int i = 0; i < 4; i++)
#pragma unroll
        for (int j = 0; j < 4; j++) acc[i][j] = 0ull;

    for (int s0 = 0; s0 < T; s0 += 32) {
#pragma unroll
        for (int it = 0; it < 8; it++) {
            int e = lid + it*256; int dd = e >> 5, sscol = e & 31;
            float val = vb[(size_t)dd*T + s0 + sscol];
            Vd[dd*35 + sscol] = fpack2(val, val);
        }
#pragma unroll
        for (int it = 0; it < 4; it++) {
            int u = lid + it*256; int sg = u & 7, tt = u >> 3;
            float4 pv = *(const float4*)&prow[(size_t)(t0+tt)*T + s0 + sg*4];
            Ps[(sg*4+0)*132 + tt] = pv.x;
            Ps[(sg*4+1)*132 + tt] = pv.y;
            Ps[(sg*4+2)*132 + tt] = pv.z;
            Ps[(sg*4+3)*132 + tt] = pv.w;
        }
        __syncthreads();
#pragma unroll
        for (int kk = 0; kk < 32; kk++) {
            ulonglong2 xa = *(const ulonglong2*)&Ps[kk*132 + tx*8];
            ulonglong2 xb = *(const ulonglong2*)&Ps[kk*132 + tx*8 + 4];
#pragma unroll
            for (int i = 0; i < 4; i++) {
                u64 w = Vd[(ty*4+i)*35 + kk];
                acc[i][0] = ffma2(w, xa.x, acc[i][0]);
                acc[i][1] = ffma2(w, xa.y, acc[i][1]);
                acc[i][2] = ffma2(w, xb.x, acc[i][2]);
                acc[i][3] = ffma2(w, xb.y, acc[i][3]);
            }
        }
        __syncthreads();
    }
#pragma unroll
    for (int dt = 0; dt < NREL; dt++) {
#pragma unroll
        for (int i = 0; i < 4; i++) {
            u64 w = rvd[dt*64 + ty*4 + i];
#pragma unroll
            for (int jp = 0; jp < 4; jp++)
                acc[i][jp] = ffma2(w, pbs[dt*64 + tx*4 + jp], acc[i][jp]);
        }
    }
#pragma unroll
    for (int i = 0; i < 4; i++) {
        float2 p0 = funpack2(acc[i][0]), p1 = funpack2(acc[i][1]);
        float2 p2 = funpack2(acc[i][2]), p3 = funpack2(acc[i][3]);
        float4 r0 = make_float4(p0.x, p0.y, p1.x, p1.y);
        float4 r1 = make_float4(p2.x, p2.y, p3.x, p3.y);
        size_t base = ((size_t)b*C + h*DK + ty*4 + i)*T + t0 + tx*8;
        *(float4*)&ctx[base]     = r0;
        *(float4*)&ctx[base + 4] = r1;
    }
}

// ---------------- channel LayerNorm -------------------------------------------
__global__ void k_ln(float* __restrict__ hbuf, const float* __restrict__ yv,
                     const float* __restrict__ g, const float* __restrict__ bb,
                     int maskOut) {
    int tx = threadIdx.x, ty = threadIdx.y;
    int t = blockIdx.x*32 + tx, b = blockIdx.y;
    float s = 0.f, s2 = 0.f;
    for (int c = ty; c < C; c += 8) {
        size_t idx = ((size_t)b*C + c)*T + t;
        float v = hbuf[idx] + yv[idx];
        s += v; s2 += v*v;
    }
    __shared__ float rs[8][32], rs2[8][32];
    rs[ty][tx] = s; rs2[ty][tx] = s2;
    __syncthreads();
    if (ty == 0) {
        for (int j = 1; j < 8; j++) { s += rs[j][tx]; s2 += rs2[j][tx]; }
        float m = s / C;
        float var = s2 / C - m*m;
        rs[0][tx] = m;
        rs2[0][tx] = rsqrtf(var + 1e-5f);
    }
    __syncthreads();
    float m = rs[0][tx], r = rs2[0][tx];
    float mk = maskOut ? g_mask[b*T + t] : 1.f;
    for (int c = ty; c < C; c += 8) {
        size_t idx = ((size_t)b*C + c)*T + t;
        float v = hbuf[idx] + yv[idx];
        hbuf[idx] = ((v - m)*r*g[c] + bb[c]) * mk;
    }
}

// ---------------- launch -------------------------------------------------------
extern "C" void kernel_launch(void* const* d_in, const int* in_sizes, int n_in,
                              void* d_out, int out_size) {
    const int*   x    = (const int*)d_in[0];
    const int*   xlen = (const int*)d_in[1];
    const float* emb  = (const float*)d_in[2];
    const float* Wq = (const float*)d_in[3],  *bq = (const float*)d_in[4];
    const float* Wk = (const float*)d_in[5],  *bk = (const float*)d_in[6];
    const float* Wv = (const float*)d_in[7],  *bv = (const float*)d_in[8];
    const float* Wo = (const float*)d_in[9],  *bo = (const float*)d_in[10];
    const float* rel_k = (const float*)d_in[11], *rel_v = (const float*)d_in[12];
    const float* ln1g = (const float*)d_in[13], *ln1b = (const float*)d_in[14];
    const float* ln2g = (const float*)d_in[15], *ln2b = (const float*)d_in[16];
    const float* w1 = (const float*)d_in[17], *b1 = (const float*)d_in[18];
    const float* w2 = (const float*)d_in[19], *b2 = (const float*)d_in[20];
    const float* pw = (const float*)d_in[21], *pbv = (const float*)d_in[22];
    float* out = (float*)d_out;
    size_t SZ = (size_t)B*C*T;

    float *ph,*pq,*pk,*pv,*pctx,*py,*pp,*pf,*pwt4,*pw1t,*pw2t,*ppwt;
    cudaGetSymbolAddress((void**)&ph,  g_h);
    cudaGetSymbolAddress((void**)&pq,  g_q);
    cudaGetSymbolAddress((void**)&pk,  g_k);
    cudaGetSymbolAddress((void**)&pv,  g_v);
    cudaGetSymbolAddress((void**)&pctx,g_ctx);
    cudaGetSymbolAddress((void**)&py,  g_y);
    cudaGetSymbolAddress((void**)&pp,  g_p);
    cudaGetSymbolAddress((void**)&pf,  g_f);
    cudaGetSymbolAddress((void**)&pwt4, g_wt4);
    cudaGetSymbolAddress((void**)&pw1t, g_w1t);
    cudaGetSymbolAddress((void**)&pw2t, g_w2t);
    cudaGetSymbolAddress((void**)&ppwt, g_pwt);

    const int BC = 136;
    int smem1 = (2*1*32*BC + 2*32*BC) * 4;   // KK=1
    int smem3 = (2*3*32*BC + 2*32*BC) * 4;   // KK=3
    static int smem_set = 0;
    if (!smem_set) {
        cudaFuncSetAttribute(k_mma<1>, cudaFuncAttributeMaxDynamicSharedMemorySize, smem1);
        cudaFuncSetAttribute(k_mma<3>, cudaFuncAttributeMaxDynamicSharedMemorySize, smem3);
        smem_set = 1;
    }

    k_embed<<<dim3(T/32, B), dim3(32,8)>>>(x, xlen, emb, out, out + 4*SZ);

    dim3 tb(32,8);
    for (int i = 0; i < LYR; i++) {
        // transpose all four C x C weight matrices for this layer
        k_transw<<<dim3(C/32, C/32), tb>>>(Wq + (size_t)i*C*C, pwt4,          C, C);
        k_transw<<<dim3(C/32, C/32), tb>>>(Wk + (size_t)i*C*C, pwt4 + C*C,    C, C);
        k_transw<<<dim3(C/32, C/32), tb>>>(Wv + (size_t)i*C*C, pwt4 + 2*C*C,  C, C);
        k_transw<<<dim3(C/32, C/32), tb>>>(Wo + (size_t)i*C*C, pwt4 + 3*C*C,  C, C);

        k_mma<1><<<dim3(T/128, C/128, B), 256, smem1>>>(pwt4,         C, bq + i*C, ph, pq, C, C, 0.125f, 0, 0, 0);
        k_mma<1><<<dim3(T/128, C/128, B), 256, smem1>>>(pwt4 + C*C,   C, bk + i*C, ph, pk, C, C, 1.f,    0, 0, 0);
        k_mma<1><<<dim3(T/128, C/128, B), 256, smem1>>>(pwt4 + 2*C*C, C, bv + i*C, ph, pv, C, C, 1.f,    0, 0, 0);
        k_qk<<<dim3(T/64, T/128, B*H), 256>>>(pq, pk, pp);
        k_relband<<<dim3(T/32, H, B), tb>>>(pq, pp, rel_k + (size_t)i*NREL*DK);
        k_softmax<<<dim3(T, H, B), 256>>>(pp);
        k_ctx<<<dim3(T/128, B*H), 256>>>(pp, pv, pctx, rel_v + (size_t)i*NREL*DK);
        k_mma<1><<<dim3(T/128, C/128, B), 256, smem1>>>(pwt4 + 3*C*C, C, bo + i*C, pctx, py, C, C, 1.f, 0, 0, 0);
        k_ln<<<dim3(T/32, B), tb>>>(ph, py, ln1g + i*C, ln1b + i*C, 0);

        k_transw<<<dim3((C*3)/32, DFF/32), tb>>>(w1 + (size_t)i*DFF*C*3, pw1t, DFF, C*3);
        k_mma<3><<<dim3(T/128, DFF/128, B), 256, smem3>>>(pw1t, DFF, b1 + i*DFF, ph, pf, DFF, C, 1.f, 1, 1, 0);
        k_transw<<<dim3((DFF*3)/32, C/32), tb>>>(w2 + (size_t)i*C*DFF*3, pw2t, C, DFF*3);
        k_mma<3><<<dim3(T/128, C/128, B), 256, smem3>>>(pw2t, C, b2 + i*C, pf, py, C, DFF, 1.f, 0, 1, 1);
        k_ln<<<dim3(T/32, B), tb>>>(ph, py, ln2g + i*C, ln2b + i*C, 1);
    }

    k_copy4<<<(B*C*T)/1024, 256>>>((const float4*)ph, (float4*)(out + SZ));
    k_transw<<<dim3(C/32, (2*C)/32), tb>>>(pw, ppwt, 2*C, C);
    k_mma<1><<<dim3(T/128, C/128, B), 256, smem1>>>(ppwt,     2*C, pbv,     ph, out + 2*SZ, C, C, 1.f, 0, 0, 1);
    k_mma<1><<<dim3(T/128, C/128, B), 256, smem1>>>(ppwt + C, 2*C, pbv + C, ph, out + 3*SZ, C, C, 1.f, 0, 0, 1);
}

// round 4
// speedup vs baseline: 3.0649x; 1.5673x over previous
#include <cuda_runtime.h>
#include <math.h>

#define B 8
#define T 512
#define C 512
#define DFF 2048
#define H 8
#define LYR 6
#define W 4
#define DK 64
#define NREL 9

typedef unsigned long long u64;
typedef unsigned int u32;

// ---------------- scratch ----------------------------------------------------
__device__ float g_h[B*C*T];
__device__ float g_q[B*C*T];
__device__ float g_k[B*C*T];
__device__ float g_v[B*C*T];
__device__ float g_ctx[B*C*T];
__device__ float g_y[B*C*T];
__device__ float g_p[(size_t)B*H*T*T];
__device__ float g_f[B*DFF*T];
__device__ float g_mask[B*T];
// packed bf16x2 hi/lo weights, layout [kp][c_pair][o]
__device__ u32 g_qkvo_hi[4*(C/2)*C], g_qkvo_lo[4*(C/2)*C];
__device__ u32 g_w1_hi[3*(C/2)*DFF], g_w1_lo[3*(C/2)*DFF];
__device__ u32 g_w2_hi[3*(DFF/2)*C], g_w2_lo[3*(DFF/2)*C];
__device__ u32 g_pj_hi[2*(C/2)*C],  g_pj_lo[2*(C/2)*C];

// ---------------- helpers ------------------------------------------------------
__device__ __forceinline__ u64 ffma2(u64 a, u64 b, u64 c) {
    u64 d; asm("fma.rn.f32x2 %0, %1, %2, %3;" : "=l"(d) : "l"(a), "l"(b), "l"(c));
    return d;
}
__device__ __forceinline__ u64 fpack2(float lo, float hi) {
    u64 d; asm("mov.b64 %0, {%1, %2};" : "=l"(d) : "f"(lo), "f"(hi));
    return d;
}
__device__ __forceinline__ float2 funpack2(u64 v) {
    float2 r; asm("mov.b64 {%0, %1}, %2;" : "=f"(r.x), "=f"(r.y) : "l"(v));
    return r;
}
// pack two f32 -> bf16x2 (hi half = h, lo half = l)
__device__ __forceinline__ u32 bf2(float h, float l) {
    u32 r; asm("cvt.rn.bf16x2.f32 %0, %1, %2;" : "=r"(r) : "f"(h), "f"(l));
    return r;
}
__device__ __forceinline__ void mma16(float* d, const u32* a, u32 b0, u32 b1) {
    asm("mma.sync.aligned.m16n8k16.row.col.f32.bf16.bf16.f32 "
        "{%0,%1,%2,%3}, {%4,%5,%6,%7}, {%8,%9}, {%0,%1,%2,%3};"
        : "+f"(d[0]), "+f"(d[1]), "+f"(d[2]), "+f"(d[3])
        : "r"(a[0]), "r"(a[1]), "r"(a[2]), "r"(a[3]), "r"(b0), "r"(b1));
}

// ---------------- embedding + mask -------------------------------------------
__global__ void k_embed(const int* __restrict__ x, const int* __restrict__ xlen,
                        const float* __restrict__ emb,
                        float* __restrict__ out_xemb, float* __restrict__ out_mask) {
    int b = blockIdx.y;
    int t = blockIdx.x * 32 + threadIdx.x;
    int xi = x[b*T + t];
    float mk = (t < xlen[b]) ? 1.f : 0.f;
    const float SQ = 22.627416997969522f;
    for (int c = threadIdx.y; c < C; c += 8) {
        float v = emb[xi*C + c] * SQ;
        out_xemb[((size_t)b*C + c)*T + t] = v;
        g_h[((size_t)b*C + c)*T + t] = v * mk;
    }
    if (threadIdx.y == 0) {
        g_mask[b*T + t] = mk;
        out_mask[b*T + t] = mk;
    }
}

__global__ void k_copy4(const float4* __restrict__ src, float4* __restrict__ dst) {
    int i = blockIdx.x * 256 + threadIdx.x;
    dst[i] = src[i];
}

// ---------------- weight pack: W[o][c*KKf+kp] -> hi/lo bf16x2 [kp][cpair][o] ---
__global__ void k_packw(const float* __restrict__ Wm, u32* __restrict__ hi,
                        u32* __restrict__ lo, int O, int Cin, int KKf, int ostride) {
    __shared__ float tile[32][33];
    int o0 = blockIdx.x*32, c0 = blockIdx.y*32, kp = blockIdx.z;
    int tx = threadIdx.x, ty = threadIdx.y;
#pragma unroll
    for (int i = 0; i < 4; i++)
        tile[tx][ty + 8*i] = Wm[(size_t)(o0 + ty + 8*i)*ostride + (size_t)(c0 + tx)*KKf + kp];
    __syncthreads();
#pragma unroll
    for (int i = 0; i < 2; i++) {
        int cp = ty + 8*i;
        float f0 = tile[2*cp][tx], f1 = tile[2*cp+1][tx];
        u32 hv = bf2(f1, f0);
        float r0 = f0 - __uint_as_float(hv << 16);
        float r1 = f1 - __uint_as_float(hv & 0xffff0000u);
        u32 lv = bf2(r1, r0);
        size_t idx = ((size_t)kp*(Cin >> 1) + (c0 >> 1) + cp)*O + o0 + tx;
        hi[idx] = hv; lo[idx] = lv;
    }
}

// ---------------- unified bf16-split mma GEMM/conv -----------------------------
// block: 128 o x NT t; 8 warps 4(M) x 2(N); warp 32 o x NT/2 t
template<int KK, int NT>
__global__ __launch_bounds__(256) void k_mma(
        const u32* __restrict__ Whi, const u32* __restrict__ Wlo,
        const float* __restrict__ bias,
        const float* __restrict__ X, float* __restrict__ Y,
        int O, int Cin, float scale, int relu, int maskIn, int maskOut) {
    const int BST = NT + 8;
    const int NCOL = NT + KK - 1;
    const int PAD = (KK - 1) / 2;
    const int NI = NT / 16;
    extern __shared__ u32 smu[];
    u32* Ahi = smu;
    u32* Alo = Ahi + KK*16*136;
    u32* Bhi = Alo + KK*16*136;
    u32* Blo = Bhi + 16*BST;

    int tid = threadIdx.x;
    int warp = tid >> 5, lane = tid & 31;
    int g = lane >> 2, tq = lane & 3;
    int wm = warp & 3, wn = warp >> 2;
    int t0 = blockIdx.x*NT, o0 = blockIdx.y*128, b = blockIdx.z;
    const float* mrow = g_mask + b*T;

    float acc[2][NI][4];
#pragma unroll
    for (int mi = 0; mi < 2; mi++)
#pragma unroll
        for (int ni = 0; ni < NI; ni++)
#pragma unroll
            for (int q = 0; q < 4; q++) acc[mi][ni][q] = 0.f;

    for (int c0 = 0; c0 < Cin; c0 += 32) {
        const int AW = KK*2048;
#pragma unroll
        for (int e = tid*4; e < AW; e += 1024) {
            int row = e >> 7, col = e & 127;
            size_t gidx = ((size_t)((row >> 4)*(Cin >> 1) + (c0 >> 1) + (row & 15)))*O + o0 + col;
            *(uint4*)&Ahi[row*136 + col] = *(const uint4*)&Whi[gidx];
            *(uint4*)&Alo[row*136 + col] = *(const uint4*)&Wlo[gidx];
        }
        for (int e = tid; e < 16*NCOL; e += 256) {
            int cp = e / NCOL, j = e - cp*NCOL;
            int t = t0 + j - PAD;
            float x0 = 0.f, x1 = 0.f;
            if (t >= 0 && t < T) {
                const float* xp = X + ((size_t)b*Cin + c0 + 2*cp)*T + t;
                x0 = xp[0]; x1 = xp[T];
                if (maskIn) { float mk = mrow[t]; x0 *= mk; x1 *= mk; }
            }
            u32 hv = bf2(x1, x0);
            float r0 = x0 - __uint_as_float(hv << 16);
            float r1 = x1 - __uint_as_float(hv & 0xffff0000u);
            Bhi[cp*BST + j] = hv;
            Blo[cp*BST + j] = bf2(r1, r0);
        }
        __syncthreads();
#pragma unroll
        for (int kp = 0; kp < KK; kp++) {
#pragma unroll
            for (int ks = 0; ks < 2; ks++) {
                int kb = ks*8;
                u32 ah[2][4], al[2][4];
#pragma unroll
                for (int mi = 0; mi < 2; mi++) {
                    int ob = wm*32 + mi*16 + g;
                    int i0 = (kp*16 + kb + tq)*136 + ob;
                    int i1 = (kp*16 + kb + tq + 4)*136 + ob;
                    ah[mi][0] = Ahi[i0]; ah[mi][1] = Ahi[i0 + 8];
                    ah[mi][2] = Ahi[i1]; ah[mi][3] = Ahi[i1 + 8];
                    al[mi][0] = Alo[i0]; al[mi][1] = Alo[i0 + 8];
                    al[mi][2] = Alo[i1]; al[mi][3] = Alo[i1 + 8];
                }
#pragma unroll
                for (int ni = 0; ni < NI; ni++) {
                    int tcol = wn*(NT/2) + ni*8 + g + kp;
                    int s0 = (kb + tq)*BST + tcol;
                    int s1 = (kb + tq + 4)*BST + tcol;
                    u32 bh0 = Bhi[s0], bh1 = Bhi[s1];
                    u32 bl0 = Blo[s0], bl1 = Blo[s1];
#pragma unroll
                    for (int mi = 0; mi < 2; mi++) {
                        mma16(acc[mi][ni], al[mi], bh0, bh1);
                        mma16(acc[mi][ni], ah[mi], bl0, bl1);
                        mma16(acc[mi][ni], ah[mi], bh0, bh1);
                    }
                }
            }
        }
        __syncthreads();
    }
#pragma unroll
    for (int mi = 0; mi < 2; mi++) {
#pragma unroll
        for (int half = 0; half < 2; half++) {
            int o = o0 + wm*32 + mi*16 + g + half*8;
            float bi = bias[o];
#pragma unroll
            for (int ni = 0; ni < NI; ni++) {
                int t = t0 + wn*(NT/2) + ni*8 + 2*tq;
                float v0 = (acc[mi][ni][half*2 + 0] + bi) * scale;
                float v1 = (acc[mi][ni][half*2 + 1] + bi) * scale;
                if (relu) { v0 = fmaxf(v0, 0.f); v1 = fmaxf(v1, 0.f); }
                if (maskOut) { v0 *= mrow[t]; v1 *= mrow[t+1]; }
                *(float2*)&Y[((size_t)b*O + o)*T + t] = make_float2(v0, v1);
            }
        }
    }
}

// ---------------- scores = q@k^T (f32x2) --------------------------------------
__global__ __launch_bounds__(256) void k_qk(const float* __restrict__ q,
                                            const float* __restrict__ k,
                                            float* __restrict__ p) {
    __shared__ u64 Qd[128*35];
    __shared__ float Ks[32*68];
    int lid = threadIdx.x;
    int tx = lid & 7, ty = lid >> 3;
    int s0 = blockIdx.x*64, t0 = blockIdx.y*128;
    int bh = blockIdx.z, b = bh >> 3, h = bh & 7;
    const float* qb = q + ((size_t)b*C + h*DK)*T;
    const float* kb = k + ((size_t)b*C + h*DK)*T;
    u64 acc[4][4];
#pragma unroll
    for (int i = 0; i < 4; i++)
#pragma unroll
        for (int j = 0; j < 4; j++) acc[i][j] = 0ull;

    for (int d0 = 0; d0 < DK; d0 += 32) {
#pragma unroll
        for (int it = 0; it < 16; it++) {
            int e = lid + it*256; int dd = e >> 7, tt = e & 127;
            float v = qb[(size_t)(d0+dd)*T + t0 + tt];
            Qd[tt*35 + dd] = fpack2(v, v);
        }
#pragma unroll
        for (int it = 0; it < 8; it++) {
            int e = lid + it*256; int r = e >> 6, cc = e & 63;
            Ks[r*68 + cc] = kb[(size_t)(d0+r)*T + s0 + cc];
        }
        __syncthreads();
#pragma unroll
        for (int kk = 0; kk < 32; kk++) {
            ulonglong2 xa = *(const ulonglong2*)&Ks[kk*68 + tx*8];
            ulonglong2 xb = *(const ulonglong2*)&Ks[kk*68 + tx*8 + 4];
#pragma unroll
            for (int i = 0; i < 4; i++) {
                u64 w = Qd[(ty*4+i)*35 + kk];
                acc[i][0] = ffma2(w, xa.x, acc[i][0]);
                acc[i][1] = ffma2(w, xa.y, acc[i][1]);
                acc[i][2] = ffma2(w, xb.x, acc[i][2]);
                acc[i][3] = ffma2(w, xb.y, acc[i][3]);
            }
        }
        __syncthreads();
    }
#pragma unroll
    for (int i = 0; i < 4; i++) {
        int t = t0 + ty*4 + i;
        float2 p0 = funpack2(acc[i][0]), p1 = funpack2(acc[i][1]);
        float2 p2 = funpack2(acc[i][2]), p3 = funpack2(acc[i][3]);
        float4 r0 = make_float4(p0.x, p0.y, p1.x, p1.y);
        float4 r1 = make_float4(p2.x, p2.y, p3.x, p3.y);
        *(float4*)&p[((size_t)bh*T + t)*T + s0 + tx*8] = r0;
        *(float4*)&p[((size_t)bh*T + t)*T + s0 + tx*8 + 4] = r1;
    }
}

// ---------------- relative band add ------------------------------------------
__global__ void k_relband(const float* __restrict__ q, float* __restrict__ p,
                          const float* __restrict__ rk) {
    __shared__ float qs[32][65];
    __shared__ float rks[NREL][64];
    int b = blockIdx.z, h = blockIdx.y, t0 = blockIdx.x*32;
    int lid = threadIdx.y*32 + threadIdx.x;
    const float* qb = q + ((size_t)b*C + h*DK)*T;
    for (int e = lid; e < 2048; e += 256) {
        int d = e >> 5, tt = e & 31;
        qs[tt][d] = qb[(size_t)d*T + t0 + tt];
    }
    for (int e = lid; e < NREL*64; e += 256) rks[e/64][e%64] = rk[e];
    __syncthreads();
    for (int w = lid; w < 32*NREL; w += 256) {
        int trow = w / NREL, dt = w % NREL;
        int t = t0 + trow, s = t + dt - W;
        if (s >= 0 && s < T) {
            float dot = 0.f;
#pragma unroll
            for (int d = 0; d < 64; d++) dot += qs[trow][d]*rks[dt][d];
            p[(((size_t)(b*H + h))*T + t)*T + s] += dot;
        }
    }
}

// ---------------- masked softmax ----------------------------------------------
__global__ void k_softmax(float* __restrict__ p) {
    int t = blockIdx.x, h = blockIdx.y, b = blockIdx.z;
    float* row = p + (((size_t)(b*H + h))*T + t)*T;
    int tid = threadIdx.x;
    float mt = g_mask[b*T + t];
    float v0 = row[tid], v1 = row[tid+256];
    if (mt * g_mask[b*T + tid]       == 0.f) v0 = -1e4f;
    if (mt * g_mask[b*T + tid + 256] == 0.f) v1 = -1e4f;
    float mx = fmaxf(v0, v1);
#pragma unroll
    for (int o = 16; o; o >>= 1) mx = fmaxf(mx, __shfl_xor_sync(0xffffffffu, mx, o));
    __shared__ float sm[8], ss[8];
    int wid = tid >> 5, lane = tid & 31;
    if (!lane) sm[wid] = mx;
    __syncthreads();
    mx = sm[0];
#pragma unroll
    for (int i = 1; i < 8; i++) mx = fmaxf(mx, sm[i]);
    float e0 = expf(v0 - mx), e1 = expf(v1 - mx);
    float s = e0 + e1;
#pragma unroll
    for (int o = 16; o; o >>= 1) s += __shfl_xor_sync(0xffffffffu, s, o);
    if (!lane) ss[wid] = s;
    __syncthreads();
    s = ss[0];
#pragma unroll
    for (int i = 1; i < 8; i++) s += ss[i];
    float inv = 1.f / s;
    row[tid]     = e0 * inv;
    row[tid+256] = e1 * inv;
}

// ---------------- ctx = p@v + band(p)@rel_v (f32x2) ----------------------------
__global__ __launch_bounds__(256) void k_ctx(const float* __restrict__ p,
                                             const float* __restrict__ v,
                                             float* __restrict__ ctx,
                                             const float* __restrict__ rv_g) {
    __shared__ u64 Vd[64*35];
    __shared__ float Ps[32*132];
    __shared__ u64 pbs[NREL*64];
    __shared__ u64 rvd[NREL*64];
    int lid = threadIdx.x;
    int tx = lid & 15, ty = lid >> 4;
    int t0 = blockIdx.x*128;
    int bh = blockIdx.y, b = bh >> 3, h = bh & 7;
    const float* vb = v + ((size_t)b*C + h*DK)*T;
    const float* prow = p + (size_t)bh*T*T;

    for (int e = lid; e < NREL*64; e += 256) rvd[e] = fpack2(rv_g[e], rv_g[e]);
    for (int e = lid; e < NREL*64; e += 256) {
        int dt = e >> 6, tp = e & 63;
        int te = t0 + tp*2;
        int se = te + dt - W, so = se + 1;
        float a = (se >= 0 && se < T) ? prow[(size_t)te*T + se] : 0.f;
        float c = (so >= 0 && so < T) ? prow[(size_t)(te+1)*T + so] : 0.f;
        pbs[e] = fpack2(a, c);
    }

    u64 acc[4][4];
#pragma unroll
    for (int i = 0; i < 4; i++)
#pragma unroll
        for (int j = 0; j < 4; j++) acc[i][j] = 0ull;

    for (int s0 = 0; s0 < T; s0 += 32) {
#pragma unroll
        for (int it = 0; it < 8; it++) {
            int e = lid + it*256; int dd = e >> 5, sscol = e & 31;
            float val = vb[(size_t)dd*T + s0 + sscol];
            Vd[dd*35 + sscol] = fpack2(val, val);
        }
#pragma unroll
        for (int it = 0; it < 4; it++) {
            int u = lid + it*256; int sg = u & 7, tt = u >> 3;
            float4 pv = *(const float4*)&prow[(size_t)(t0+tt)*T + s0 + sg*4];
            Ps[(sg*4+0)*132 + tt] = pv.x;
            Ps[(sg*4+1)*132 + tt] = pv.y;
            Ps[(sg*4+2)*132 + tt] = pv.z;
            Ps[(sg*4+3)*132 + tt] = pv.w;
        }
        __syncthreads();
#pragma unroll
        for (int kk = 0; kk < 32; kk++) {
            ulonglong2 xa = *(const ulonglong2*)&Ps[kk*132 + tx*8];
            ulonglong2 xb = *(const ulonglong2*)&Ps[kk*132 + tx*8 + 4];
#pragma unroll
            for (int i = 0; i < 4; i++) {
                u64 w = Vd[(ty*4+i)*35 + kk];
                acc[i][0] = ffma2(w, xa.x, acc[i][0]);
                acc[i][1] = ffma2(w, xa.y, acc[i][1]);
                acc[i][2] = ffma2(w, xb.x, acc[i][2]);
                acc[i][3] = ffma2(w, xb.y, acc[i][3]);
            }
        }
        __syncthreads();
    }
#pragma unroll
    for (int dt = 0; dt < NREL; dt++) {
#pragma unroll
        for (int i = 0; i < 4; i++) {
            u64 w = rvd[dt*64 + ty*4 + i];
#pragma unroll
            for (int jp = 0; jp < 4; jp++)
                acc[i][jp] = ffma2(w, pbs[dt*64 + tx*4 + jp], acc[i][jp]);
        }
    }
#pragma unroll
    for (int i = 0; i < 4; i++) {
        float2 p0 = funpack2(acc[i][0]), p1 = funpack2(acc[i][1]);
        float2 p2 = funpack2(acc[i][2]), p3 = funpack2(acc[i][3]);
        float4 r0 = make_float4(p0.x, p0.y, p1.x, p1.y);
        float4 r1 = make_float4(p2.x, p2.y, p3.x, p3.y);
        size_t base = ((size_t)b*C + h*DK + ty*4 + i)*T + t0 + tx*8;
        *(float4*)&ctx[base]     = r0;
        *(float4*)&ctx[base + 4] = r1;
    }
}

// ---------------- channel LayerNorm -------------------------------------------
__global__ void k_ln(float* __restrict__ hbuf, const float* __restrict__ yv,
                     const float* __restrict__ g, const float* __restrict__ bb,
                     int maskOut) {
    int tx = threadIdx.x, ty = threadIdx.y;
    int t = blockIdx.x*32 + tx, b = blockIdx.y;
    float s = 0.f, s2 = 0.f;
    for (int c = ty; c < C; c += 8) {
        size_t idx = ((size_t)b*C + c)*T + t;
        float v = hbuf[idx] + yv[idx];
        s += v; s2 += v*v;
    }
    __shared__ float rs[8][32], rs2[8][32];
    rs[ty][tx] = s; rs2[ty][tx] = s2;
    __syncthreads();
    if (ty == 0) {
        for (int j = 1; j < 8; j++) { s += rs[j][tx]; s2 += rs2[j][tx]; }
        float m = s / C;
        float var = s2 / C - m*m;
        rs[0][tx] = m;
        rs2[0][tx] = rsqrtf(var + 1e-5f);
    }
    __syncthreads();
    float m = rs[0][tx], r = rs2[0][tx];
    float mk = maskOut ? g_mask[b*T + t] : 1.f;
    for (int c = ty; c < C; c += 8) {
        size_t idx = ((size_t)b*C + c)*T + t;
        float v = hbuf[idx] + yv[idx];
        hbuf[idx] = ((v - m)*r*g[c] + bb[c]) * mk;
    }
}

// ---------------- launch -------------------------------------------------------
extern "C" void kernel_launch(void* const* d_in, const int* in_sizes, int n_in,
                              void* d_out, int out_size) {
    const int*   x    = (const int*)d_in[0];
    const int*   xlen = (const int*)d_in[1];
    const float* emb  = (const float*)d_in[2];
    const float* Wq = (const float*)d_in[3],  *bq = (const float*)d_in[4];
    const float* Wk = (const float*)d_in[5],  *bk = (const float*)d_in[6];
    const float* Wv = (const float*)d_in[7],  *bv = (const float*)d_in[8];
    const float* Wo = (const float*)d_in[9],  *bo = (const float*)d_in[10];
    const float* rel_k = (const float*)d_in[11], *rel_v = (const float*)d_in[12];
    const float* ln1g = (const float*)d_in[13], *ln1b = (const float*)d_in[14];
    const float* ln2g = (const float*)d_in[15], *ln2b = (const float*)d_in[16];
    const float* w1 = (const float*)d_in[17], *b1 = (const float*)d_in[18];
    const float* w2 = (const float*)d_in[19], *b2 = (const float*)d_in[20];
    const float* pw = (const float*)d_in[21], *pbv = (const float*)d_in[22];
    float* out = (float*)d_out;
    size_t SZ = (size_t)B*C*T;

    float *ph,*pq,*pk,*pv,*pctx,*py,*pp,*pf;
    u32 *qoh,*qol,*w1h,*w1l,*w2h,*w2l,*pjh,*pjl;
    cudaGetSymbolAddress((void**)&ph,  g_h);
    cudaGetSymbolAddress((void**)&pq,  g_q);
    cudaGetSymbolAddress((void**)&pk,  g_k);
    cudaGetSymbolAddress((void**)&pv,  g_v);
    cudaGetSymbolAddress((void**)&pctx,g_ctx);
    cudaGetSymbolAddress((void**)&py,  g_y);
    cudaGetSymbolAddress((void**)&pp,  g_p);
    cudaGetSymbolAddress((void**)&pf,  g_f);
    cudaGetSymbolAddress((void**)&qoh, g_qkvo_hi);
    cudaGetSymbolAddress((void**)&qol, g_qkvo_lo);
    cudaGetSymbolAddress((void**)&w1h, g_w1_hi);
    cudaGetSymbolAddress((void**)&w1l, g_w1_lo);
    cudaGetSymbolAddress((void**)&w2h, g_w2_hi);
    cudaGetSymbolAddress((void**)&w2l, g_w2_lo);
    cudaGetSymbolAddress((void**)&pjh, g_pj_hi);
    cudaGetSymbolAddress((void**)&pjl, g_pj_lo);

    const int smem_g  = (1*16*136 + 16*72)  * 2 * 4;  // k_mma<1,64>
    const int smem_c1 = (3*16*136 + 16*136) * 2 * 4;  // k_mma<3,128>
    const int smem_c2 = (3*16*136 + 16*72)  * 2 * 4;  // k_mma<3,64>
    static int attr_set = 0;
    if (!attr_set) {
        cudaFuncSetAttribute(k_mma<3,128>, cudaFuncAttributeMaxDynamicSharedMemorySize, smem_c1);
        cudaFuncSetAttribute(k_mma<3,64>,  cudaFuncAttributeMaxDynamicSharedMemorySize, smem_c2);
        attr_set = 1;
    }

    dim3 tb(32,8);
    const int WSTEP = (C/2)*C;  // u32 per packed CxC matrix

    k_embed<<<dim3(T/32, B), dim3(32,8)>>>(x, xlen, emb, out, out + 4*SZ);
    // pack proj halves once
    k_packw<<<dim3(C/32, C/32, 1), tb>>>(pw,                 pjh,         pjl,         C, C, 1, C);
    k_packw<<<dim3(C/32, C/32, 1), tb>>>(pw + (size_t)C*C,   pjh + WSTEP, pjl + WSTEP, C, C, 1, C);

    for (int i = 0; i < LYR; i++) {
        k_packw<<<dim3(C/32, C/32, 1), tb>>>(Wq + (size_t)i*C*C, qoh,           qol,           C, C, 1, C);
        k_packw<<<dim3(C/32, C/32, 1), tb>>>(Wk + (size_t)i*C*C, qoh + WSTEP,   qol + WSTEP,   C, C, 1, C);
        k_packw<<<dim3(C/32, C/32, 1), tb>>>(Wv + (size_t)i*C*C, qoh + 2*WSTEP, qol + 2*WSTEP, C, C, 1, C);
        k_packw<<<dim3(C/32, C/32, 1), tb>>>(Wo + (size_t)i*C*C, qoh + 3*WSTEP, qol + 3*WSTEP, C, C, 1, C);
        k_packw<<<dim3(DFF/32, C/32, 3), tb>>>(w1 + (size_t)i*DFF*C*3, w1h, w1l, DFF, C, 3, C*3);
        k_packw<<<dim3(C/32, DFF/32, 3), tb>>>(w2 + (size_t)i*C*DFF*3, w2h, w2l, C, DFF, 3, DFF*3);

        k_mma<1,64><<<dim3(T/64, C/128, B), 256, smem_g>>>(qoh,           qol,           bq + i*C, ph, pq, C, C, 0.125f, 0, 0, 0);
        k_mma<1,64><<<dim3(T/64, C/128, B), 256, smem_g>>>(qoh + WSTEP,   qol + WSTEP,   bk + i*C, ph, pk, C, C, 1.f,    0, 0, 0);
        k_mma<1,64><<<dim3(T/64, C/128, B), 256, smem_g>>>(qoh + 2*WSTEP, qol + 2*WSTEP, bv + i*C, ph, pv, C, C, 1.f,    0, 0, 0);
        k_qk<<<dim3(T/64, T/128, B*H), 256>>>(pq, pk, pp);
        k_relband<<<dim3(T/32, H, B), tb>>>(pq, pp, rel_k + (size_t)i*NREL*DK);
        k_softmax<<<dim3(T, H, B), 256>>>(pp);
        k_ctx<<<dim3(T/128, B*H), 256>>>(pp, pv, pctx, rel_v + (size_t)i*NREL*DK);
        k_mma<1,64><<<dim3(T/64, C/128, B), 256, smem_g>>>(qoh + 3*WSTEP, qol + 3*WSTEP, bo + i*C, pctx, py, C, C, 1.f, 0, 0, 0);
        k_ln<<<dim3(T/32, B), tb>>>(ph, py, ln1g + i*C, ln1b + i*C, 0);

        k_mma<3,128><<<dim3(T/128, DFF/128, B), 256, smem_c1>>>(w1h, w1l, b1 + i*DFF, ph, pf, DFF, C, 1.f, 1, 1, 0);
        k_mma<3,64><<<dim3(T/64, C/128, B), 256, smem_c2>>>(w2h, w2l, b2 + i*C, pf, py, C, DFF, 1.f, 0, 1, 1);
        k_ln<<<dim3(T/32, B), tb>>>(ph, py, ln2g + i*C, ln2b + i*C, 1);
    }

    k_copy4<<<(B*C*T)/1024, 256>>>((const float4*)ph, (float4*)(out + SZ));
    k_mma<1,64><<<dim3(T/64, C/128, B), 256, smem_g>>>(pjh,         pjl,         pbv,     ph, out + 2*SZ, C, C, 1.f, 0, 0, 1);
    k_mma<1,64><<<dim3(T/64, C/128, B), 256, smem_g>>>(pjh + WSTEP, pjl + WSTEP, pbv + C, ph, out + 3*SZ, C, C, 1.f, 0, 0, 1);
}

// round 6
// speedup vs baseline: 3.4444x; 1.1238x over previous
#include <cuda_runtime.h>
#include <math.h>

#define B 8
#define T 512
#define C 512
#define DFF 2048
#define H 8
#define LYR 6
#define W 4
#define DK 64
#define NREL 9

typedef unsigned long long u64;
typedef unsigned int u32;

// ---------------- scratch ----------------------------------------------------
__device__ float g_h[B*C*T];
__device__ float g_qkv[B*3*C*T];
__device__ float g_ctx[B*C*T];
__device__ float g_y[B*C*T];
__device__ float g_p[(size_t)B*H*T*T];
__device__ float g_f[B*DFF*T];
__device__ float g_mask[B*T];
__device__ float g_b3[3*C];
// activation panels, pair-major: [b][ct][pair 32][516], bf16x2 hi/lo
__device__ u32 g_px512_hi[B*8*32*516],   g_px512_lo[B*8*32*516];
__device__ u32 g_px2048_hi[B*32*32*516], g_px2048_lo[B*32*32*516];
// weight fragment arrays: [kp][c16][ot][slot8][lane32][4regs] u32
__device__ u32 g_wqkv_hi[32*12*1024],  g_wqkv_lo[32*12*1024];
__device__ u32 g_wo_hi[32*4*1024],     g_wo_lo[32*4*1024];
__device__ u32 g_w1_hi[3*32*16*1024],  g_w1_lo[3*32*16*1024];
__device__ u32 g_w2_hi[3*128*4*1024],  g_w2_lo[3*128*4*1024];
__device__ u32 g_pj_hi[32*8*1024],     g_pj_lo[32*8*1024];

// ---------------- helpers ------------------------------------------------------
__device__ __forceinline__ u64 ffma2(u64 a, u64 b, u64 c) {
    u64 d; asm("fma.rn.f32x2 %0, %1, %2, %3;" : "=l"(d) : "l"(a), "l"(b), "l"(c));
    return d;
}
__device__ __forceinline__ u64 fpack2(float lo, float hi) {
    u64 d; asm("mov.b64 %0, {%1, %2};" : "=l"(d) : "f"(lo), "f"(hi));
    return d;
}
__device__ __forceinline__ float2 funpack2(u64 v) {
    float2 r; asm("mov.b64 {%0, %1}, %2;" : "=f"(r.x), "=f"(r.y) : "l"(v));
    return r;
}
__device__ __forceinline__ u32 bf2(float h, float l) {
    u32 r; asm("cvt.rn.bf16x2.f32 %0, %1, %2;" : "=r"(r) : "f"(h), "f"(l));
    return r;
}
__device__ __forceinline__ void mma16(float* d, const u32* a, u32 b0, u32 b1) {
    asm("mma.sync.aligned.m16n8k16.row.col.f32.bf16.bf16.f32 "
        "{%0,%1,%2,%3}, {%4,%5,%6,%7}, {%8,%9}, {%0,%1,%2,%3};"
        : "+f"(d[0]), "+f"(d[1]), "+f"(d[2]), "+f"(d[3])
        : "r"(a[0]), "r"(a[1]), "r"(a[2]), "r"(a[3]), "r"(b0), "r"(b1));
}
__device__ __forceinline__ u32 smem_u32(const void* p) {
    u32 a; asm("{ .reg .u64 t; cvta.to.shared.u64 t, %1; cvt.u32.u64 %0, t; }"
               : "=r"(a) : "l"(p));
    return a;
}
__device__ __forceinline__ void cp16(u32 dst, const void* src) {
    asm volatile("{ .reg .u64 g; cvta.to.global.u64 g, %1; "
                 "cp.async.cg.shared.global [%0], [g], 16; }"
                 :: "r"(dst), "l"(src) : "memory");
}

// ---------------- embedding + mask -------------------------------------------
__global__ void k_embed(const int* __restrict__ x, const int* __restrict__ xlen,
                        const float* __restrict__ emb,
                        float* __restrict__ out_xemb, float* __restrict__ out_mask) {
    int b = blockIdx.y;
    int t = blockIdx.x * 32 + threadIdx.x;
    int xi = x[b*T + t];
    float mk = (t < xlen[b]) ? 1.f : 0.f;
    const float SQ = 22.627416997969522f;
    for (int c = threadIdx.y; c < C; c += 8) {
        float v = emb[xi*C + c] * SQ;
        out_xemb[((size_t)b*C + c)*T + t] = v;
        g_h[((size_t)b*C + c)*T + t] = v * mk;
    }
    if (threadIdx.y == 0) {
        g_mask[b*T + t] = mk;
        out_mask[b*T + t] = mk;
    }
}

__global__ void k_copy4(const float4* __restrict__ src, float4* __restrict__ dst) {
    int i = blockIdx.x * 256 + threadIdx.x;
    dst[i] = src[i];
}

__global__ void k_bias3(const float* __restrict__ bq, const float* __restrict__ bk,
                        const float* __restrict__ bv, float* __restrict__ b3) {
    int i = blockIdx.x*256 + threadIdx.x;
    b3[i] = (i < 512) ? bq[i]*0.125f : (i < 1024 ? bk[i-512] : bv[i-1024]);
}

// ---------------- weight pack -> per-lane mma fragment order -------------------
__global__ void k_packwf(const float* __restrict__ Wm, float scale,
                         u32* __restrict__ hi, u32* __restrict__ lo,
                         int ostride, int KKf, int CT16, int OT, int otOff) {
    int ot = blockIdx.x, c16 = blockIdx.y, kp = blockIdx.z;
    int tid = threadIdx.x, s = tid >> 5, l = tid & 31;
    int g = l >> 2, tq = l & 3;
    int wm = s >> 2, mi = s & 3;
    int obase = ot*128 + wm*64 + mi*16 + g;
    u32 rh[4], rl[4];
#pragma unroll
    for (int r = 0; r < 4; r++) {
        int o = obase + (r & 1)*8;
        int pair = (r < 2) ? tq : tq + 4;
        int ce = c16*16 + 2*pair;
        float f0 = Wm[(size_t)o*ostride + (size_t)ce*KKf + kp] * scale;
        float f1 = Wm[(size_t)o*ostride + (size_t)(ce+1)*KKf + kp] * scale;
        u32 hv = bf2(f1, f0);
        float r0 = f0 - __uint_as_float(hv << 16);
        float r1 = f1 - __uint_as_float(hv & 0xffff0000u);
        rh[r] = hv; rl[r] = bf2(r1, r0);
    }
    size_t base = ((size_t)((kp*CT16 + c16)*OT + otOff + ot))*1024 + (s*32 + l)*4;
    *(uint4*)&hi[base] = make_uint4(rh[0], rh[1], rh[2], rh[3]);
    *(uint4*)&lo[base] = make_uint4(rl[0], rl[1], rl[2], rl[3]);
}

// ---------------- activation pack: f32 [b][c][t] -> pair-major padded panels ----
__global__ void k_packx(const float* __restrict__ X, u32* __restrict__ Phi,
                        u32* __restrict__ Plo, int Cin, int useMask) {
    __shared__ float tile[64][65];
    int t0 = blockIdx.x*64, ct = blockIdx.y, b = blockIdx.z;
    int CT = gridDim.y;
    int tid = threadIdx.x;
    int tx = tid & 63, ty = tid >> 6;
    float mk = useMask ? g_mask[b*T + t0 + tx] : 1.f;
#pragma unroll
    for (int i = 0; i < 16; i++) {
        int cc = ty + i*4;
        tile[cc][tx] = X[((size_t)b*Cin + ct*64 + cc)*T + t0 + tx] * mk;
    }
    __syncthreads();
    size_t base = (size_t)(b*CT + ct)*32*516;
#pragma unroll
    for (int i = 0; i < 8; i++) {
        int e = tid + i*256;
        int p = e >> 6, tt = e & 63;
        float f0 = tile[2*p][tt], f1 = tile[2*p+1][tt];
        u32 hv = bf2(f1, f0);
        float r0 = f0 - __uint_as_float(hv << 16);
        float r1 = f1 - __uint_as_float(hv & 0xffff0000u);
        Phi[base + (size_t)p*516 + t0 + tt + 1] = hv;
        Plo[base + (size_t)p*516 + t0 + tt + 1] = bf2(r1, r0);
    }
    if (t0 == 0 && tid < 32) {
        Phi[base + (size_t)tid*516] = 0u; Plo[base + (size_t)tid*516] = 0u;
    }
    if (t0 == T-64 && tid < 96) {
        int p = tid/3, j = 513 + tid%3;
        Phi[base + (size_t)p*516 + j] = 0u; Plo[base + (size_t)p*516 + j] = 0u;
    }
}

// ---------------- fragment-direct bf16 mma GEMM/conv ---------------------------
// block 128 o x 128 t; 8 warps 2(M)x4(N); warp 64 o x 32 t; A from GMEM frags,
// B from double-buffered cp.async smem panel.
template<int KK, int NT>
__global__ __launch_bounds__(256, 2) void k_mma_f(
        const u32* __restrict__ Whi, const u32* __restrict__ Wlo,
        const u32* __restrict__ Xhi, const u32* __restrict__ Xlo,
        const float* __restrict__ bias,
        float* __restrict__ Y0, float* __restrict__ Y1,
        int Osplit, int Cin, int relu, int maskOut) {
    extern __shared__ char smc[];
    const int STG = 64*136;          // u32 per stage
    const int CHUNKS = (NT + 4) / 4;
    const int PAD = (KK - 1) / 2;
    u32 sb = smem_u32(smc);
    int tid = threadIdx.x, warp = tid >> 5, lane = tid & 31;
    int g = lane >> 2, tq = lane & 3;
    int wm = warp >> 2, wn = warp & 3;
    int t0 = blockIdx.x*NT, oy = blockIdx.y, b = blockIdx.z;
    int OT = gridDim.y;
    int CT = Cin >> 6, CT16 = Cin >> 4;
    const float* mrow = g_mask + b*T;

    float acc[4][4][4];
#pragma unroll
    for (int mi = 0; mi < 4; mi++)
#pragma unroll
        for (int ni = 0; ni < 4; ni++)
#pragma unroll
            for (int q = 0; q < 4; q++) acc[mi][ni][q] = 0.f;

    // prologue copy: ct=0 -> stage 0
    {
        size_t prow = (size_t)(b*CT)*32;
        for (int e = tid; e < 64*CHUNKS; e += 256) {
            int r = e / CHUNKS, cch = e - r*CHUNKS;
            const u32* src = ((r < 32) ? Xhi : Xlo) + (prow + (r & 31))*516 + t0 + cch*4;
            cp16(sb + (u32)(r*136 + cch*4)*4, src);
        }
        asm volatile("cp.async.commit_group;" ::: "memory");
    }

    for (int ct = 0; ct < CT; ct++) {
        if (ct + 1 < CT) {
            int stage = (ct + 1) & 1;
            size_t prow = (size_t)(b*CT + ct + 1)*32;
            for (int e = tid; e < 64*CHUNKS; e += 256) {
                int r = e / CHUNKS, cch = e - r*CHUNKS;
                const u32* src = ((r < 32) ? Xhi : Xlo) + (prow + (r & 31))*516 + t0 + cch*4;
                cp16(sb + (u32)(stage*STG + r*136 + cch*4)*4, src);
            }
            asm volatile("cp.async.commit_group;" ::: "memory");
            asm volatile("cp.async.wait_group 1;" ::: "memory");
        } else {
            asm volatile("cp.async.wait_group 0;" ::: "memory");
        }
        __syncthreads();
        const u32* Bst = (const u32*)smc + (ct & 1)*STG;
#pragma unroll
        for (int kp = 0; kp < KK; kp++) {
            int ccoff = kp + 1 - PAD;
#pragma unroll
            for (int k16 = 0; k16 < 4; k16++) {
                size_t ab = ((size_t)((kp*CT16 + ct*4 + k16)*OT + oy)) << 8;
                const uint4* Abh = (const uint4*)Whi + ab;
                const uint4* Abl = (const uint4*)Wlo + ab;
                uint4 ah[4], al[4];
#pragma unroll
                for (int mi = 0; mi < 4; mi++) {
                    int s = (wm*4 + mi)*32 + lane;
                    ah[mi] = Abh[s]; al[mi] = Abl[s];
                }
                int rb = k16*8;
#pragma unroll
                for (int ni = 0; ni < 4; ni++) {
                    int cc = wn*32 + ni*8 + g + ccoff;
                    u32 bh0 = Bst[(rb+tq)*136 + cc];
                    u32 bh1 = Bst[(rb+tq+4)*136 + cc];
                    u32 bl0 = Bst[(32+rb+tq)*136 + cc];
                    u32 bl1 = Bst[(32+rb+tq+4)*136 + cc];
#pragma unroll
                    for (int mi = 0; mi < 4; mi++) {
                        mma16(acc[mi][ni], (const u32*)&al[mi], bh0, bh1);
                        mma16(acc[mi][ni], (const u32*)&ah[mi], bl0, bl1);
                        mma16(acc[mi][ni], (const u32*)&ah[mi], bh0, bh1);
                    }
                }
            }
        }
        __syncthreads();
    }
    // epilogue
#pragma unroll
    for (int mi = 0; mi < 4; mi++) {
#pragma unroll
        for (int half = 0; half < 2; half++) {
            int o = oy*128 + wm*64 + mi*16 + g + half*8;
            float bi = bias[o];
            float* Yp; size_t rowb;
            if (o < Osplit) { Yp = Y0; rowb = ((size_t)b*Osplit + o)*T; }
            else            { Yp = Y1; rowb = ((size_t)b*Osplit + (o - Osplit))*T; }
#pragma unroll
            for (int ni = 0; ni < 4; ni++) {
                int t = t0 + wn*32 + ni*8 + 2*tq;
                float v0 = acc[mi][ni][half*2 + 0] + bi;
                float v1 = acc[mi][ni][half*2 + 1] + bi;
                if (relu) { v0 = fmaxf(v0, 0.f); v1 = fmaxf(v1, 0.f); }
                if (maskOut) { v0 *= mrow[t]; v1 *= mrow[t+1]; }
                *(float2*)&Yp[rowb + t] = make_float2(v0, v1);
            }
        }
    }
}

// ---------------- scores = q@k^T (f32x2), fused-qkv input ----------------------
__global__ __launch_bounds__(256) void k_qk(const float* __restrict__ qkv,
                                            float* __restrict__ p) {
    __shared__ u64 Qd[128*35];
    __shared__ float Ks[32*68];
    int lid = threadIdx.x;
    int tx = lid & 7, ty = lid >> 3;
    int s0 = blockIdx.x*64, t0 = blockIdx.y*128;
    int bh = blockIdx.z, b = bh >> 3, h = bh & 7;
    const float* qb = qkv + ((size_t)b*1536 + h*DK)*T;
    const float* kb = qkv + ((size_t)b*1536 + 512 + h*DK)*T;
    u64 acc[4][4];
#pragma unroll
    for (int i = 0; i < 4; i++)
#pragma unroll
        for (int j = 0; j < 4; j++) acc[i][j] = 0ull;

    for (int d0 = 0; d0 < DK; d0 += 32) {
#pragma unroll
        for (int it = 0; it < 16; it++) {
            int e = lid + it*256; int dd = e >> 7, tt = e & 127;
            float v = qb[(size_t)(d0+dd)*T + t0 + tt];
            Qd[tt*35 + dd] = fpack2(v, v);
        }
#pragma unroll
        for (int it = 0; it < 8; it++) {
            int e = lid + it*256; int r = e >> 6, cc = e & 63;
            Ks[r*68 + cc] = kb[(size_t)(d0+r)*T + s0 + cc];
        }
        __syncthreads();
#pragma unroll
        for (int kk = 0; kk < 32; kk++) {
            ulonglong2 xa = *(const ulonglong2*)&Ks[kk*68 + tx*8];
            ulonglong2 xb = *(const ulonglong2*)&Ks[kk*68 + tx*8 + 4];
#pragma unroll
            for (int i = 0; i < 4; i++) {
                u64 w = Qd[(ty*4+i)*35 + kk];
                acc[i][0] = ffma2(w, xa.x, acc[i][0]);
                acc[i][1] = ffma2(w, xa.y, acc[i][1]);
                acc[i][2] = ffma2(w, xb.x, acc[i][2]);
                acc[i][3] = ffma2(w, xb.y, acc[i][3]);
            }
        }
        __syncthreads();
    }
#pragma unroll
    for (int i = 0; i < 4; i++) {
        int t = t0 + ty*4 + i;
        float2 p0 = funpack2(acc[i][0]), p1 = funpack2(acc[i][1]);
        float2 p2 = funpack2(acc[i][2]), p3 = funpack2(acc[i][3]);
        float4 r0 = make_float4(p0.x, p0.y, p1.x, p1.y);
        float4 r1 = make_float4(p2.x, p2.y, p3.x, p3.y);
        *(float4*)&p[((size_t)bh*T + t)*T + s0 + tx*8] = r0;
        *(float4*)&p[((size_t)bh*T + t)*T + s0 + tx*8 + 4] = r1;
    }
}

// ---------------- relative band add ------------------------------------------
__global__ void k_relband(const float* __restrict__ qkv, float* __restrict__ p,
                          const float* __restrict__ rk) {
    __shared__ float qs[32][65];
    __shared__ float rks[NREL][64];
    int b = blockIdx.z, h = blockIdx.y, t0 = blockIdx.x*32;
    int lid = threadIdx.y*32 + threadIdx.x;
    const float* qb = qkv + ((size_t)b*1536 + h*DK)*T;
    for (int e = lid; e < 2048; e += 256) {
        int d = e >> 5, tt = e & 31;
        qs[tt][d] = qb[(size_t)d*T + t0 + tt];
    }
    for (int e = lid; e < NREL*64; e += 256) rks[e/64][e%64] = rk[e];
    __syncthreads();
    for (int w = lid; w < 32*NREL; w += 256) {
        int trow = w / NREL, dt = w % NREL;
        int t = t0 + trow, s = t + dt - W;
        if (s >= 0 && s < T) {
            float dot = 0.f;
#pragma unroll
            for (int d = 0; d < 64; d++) dot += qs[trow][d]*rks[dt][d];
            p[(((size_t)(b*H + h))*T + t)*T + s] += dot;
        }
    }
}

// ---------------- masked softmax ----------------------------------------------
__global__ void k_softmax(float* __restrict__ p) {
    int t = blockIdx.x, h = blockIdx.y, b = blockIdx.z;
    float* row = p + (((size_t)(b*H + h))*T + t)*T;
    int tid = threadIdx.x;
    float mt = g_mask[b*T + t];
    float v0 = row[tid], v1 = row[tid+256];
    if (mt * g_mask[b*T + tid]       == 0.f) v0 = -1e4f;
    if (mt * g_mask[b*T + tid + 256] == 0.f) v1 = -1e4f;
    float mx = fmaxf(v0, v1);
#pragma unroll
    for (int o = 16; o; o >>= 1) mx = fmaxf(mx, __shfl_xor_sync(0xffffffffu, mx, o));
    __shared__ float sm[8], ss[8];
    int wid = tid >> 5, lane = tid & 31;
    if (!lane) sm[wid] = mx;
    __syncthreads();
    mx = sm[0];
#pragma unroll
    for (int i = 1; i < 8; i++) mx = fmaxf(mx, sm[i]);
    float e0 = expf(v0 - mx), e1 = expf(v1 - mx);
    float s = e0 + e1;
#pragma unroll
    for (int o = 16; o; o >>= 1) s += __shfl_xor_sync(0xffffffffu, s, o);
    if (!lane) ss[wid] = s;
    __syncthreads();
    s = ss[0];
#pragma unroll
    for (int i = 1; i < 8; i++) s += ss[i];
    float inv = 1.f / s;
    row[tid]     = e0 * inv;
    row[tid+256] = e1 * inv;
}

// ---------------- ctx = p@v + band(p)@rel_v (f32x2) ----------------------------
__global__ __launch_bounds__(256) void k_ctx(const float* __restrict__ p,
                                             const float* __restrict__ qkv,
                                             float* __restrict__ ctx,
                                             const float* __restrict__ rv_g) {
    __shared__ u64 Vd[64*35];
    __shared__ float Ps[32*132];
    __shared__ u64 pbs[NREL*64];
    __shared__ u64 rvd[NREL*64];
    int lid = threadIdx.x;
    int tx = lid & 15, ty = lid >> 4;
    int t0 = blockIdx.x*128;
    int bh = blockIdx.y, b = bh >> 3, h = bh & 7;
    const float* vb = qkv + ((size_t)b*1536 + 1024 + h*DK)*T;
    const float* prow = p + (size_t)bh*T*T;

    for (int e = lid; e < NREL*64; e += 256) rvd[e] = fpack2(rv_g[e], rv_g[e]);
    for (int e = lid; e < NREL*64; e += 256) {
        int dt = e >> 6, tp = e & 63;
        int te = t0 + tp*2;
        int se = te + dt - W, so = se + 1;
        float a = (se >= 0 && se < T) ? prow[(size_t)te*T + se] : 0.f;
        float c = (so >= 0 && so < T) ? prow[(size_t)(te+1)*T + so] : 0.f;
        pbs[e] = fpack2(a, c);
    }

    u64 acc[4][4];
#pragma unroll
    for (int i = 0; i < 4; i++)
#pragma unroll
        for (int j = 0; j < 4; j++) acc[i][j] = 0ull;

    for (int s0 = 0; s0 < T; s0 += 32) {
#pragma unroll
        for (int it = 0; it < 8; it++) {
            int e = lid + it*256; int dd = e >> 5, sscol = e & 31;
            float val = vb[(size_t)dd*T + s0 + sscol];
            Vd[dd*35 + sscol] = fpack2(val, val);
        }
#pragma unroll
        for (int it = 0; it < 4; it++) {
            int u = lid + it*256; int sg = u & 7, tt = u >> 3;
            float4 pv = *(const float4*)&prow[(size_t)(t0+tt)*T + s0 + sg*4];
            Ps[(sg*4+0)*132 + tt] = pv.x;
            Ps[(sg*4+1)*132 + tt] = pv.y;
            Ps[(sg*4+2)*132 + tt] = pv.z;
            Ps[(sg*4+3)*132 + tt] = pv.w;
        }
        __syncthreads();
#pragma unroll
        for (int kk = 0; kk < 32; kk++) {
            ulonglong2 xa = *(const ulonglong2*)&Ps[kk*132 + tx*8];
            ulonglong2 xb = *(const ulonglong2*)&Ps[kk*132 + tx*8 + 4];
#pragma unroll
            for (int i = 0; i < 4; i++) {
                u64 w = Vd[(ty*4+i)*35 + kk];
                acc[i][0] = ffma2(w, xa.x, acc[i][0]);
                acc[i][1] = ffma2(w, xa.y, acc[i][1]);
                acc[i][2] = ffma2(w, xb.x, acc[i][2]);
                acc[i][3] = ffma2(w, xb.y, acc[i][3]);
            }
        }
        __syncthreads();
    }
#pragma unroll
    for (int dt = 0; dt < NREL; dt++) {
#pragma unroll
        for (int i = 0; i < 4; i++) {
            u64 w = rvd[dt*64 + ty*4 + i];
#pragma unroll
            for (int jp = 0; jp < 4; jp++)
                acc[i][jp] = ffma2(w, pbs[dt*64 + tx*4 + jp], acc[i][jp]);
        }
    }
#pragma unroll
    for (int i = 0; i < 4; i++) {
        float2 p0 = funpack2(acc[i][0]), p1 = funpack2(acc[i][1]);
        float2 p2 = funpack2(acc[i][2]), p3 = funpack2(acc[i][3]);
        float4 r0 = make_float4(p0.x, p0.y, p1.x, p1.y);
        float4 r1 = make_float4(p2.x, p2.y, p3.x, p3.y);
        size_t base = ((size_t)b*C + h*DK + ty*4 + i)*T + t0 + tx*8;
        *(float4*)&ctx[base]     = r0;
        *(float4*)&ctx[base + 4] = r1;
    }
}

// ---------------- channel LayerNorm -------------------------------------------
__global__ void k_ln(float* __restrict__ hbuf, const float* __restrict__ yv,
                     const float* __restrict__ g, const float* __restrict__ bb,
                     int maskOut) {
    int tx = threadIdx.x, ty = threadIdx.y;
    int t = blockIdx.x*32 + tx, b = blockIdx.y;
    float s = 0.f, s2 = 0.f;
    for (int c = ty; c < C; c += 8) {
        size_t idx = ((size_t)b*C + c)*T + t;
        float v = hbuf[idx] + yv[idx];
        s += v; s2 += v*v;
    }
    __shared__ float rs[8][32], rs2[8][32];
    rs[ty][tx] = s; rs2[ty][tx] = s2;
    __syncthreads();
    if (ty == 0) {
        for (int j = 1; j < 8; j++) { s += rs[j][tx]; s2 += rs2[j][tx]; }
        float m = s / C;
        float var = s2 / C - m*m;
        rs[0][tx] = m;
        rs2[0][tx] = rsqrtf(var + 1e-5f);
    }
    __syncthreads();
    float m = rs[0][tx], r = rs2[0][tx];
    float mk = maskOut ? g_mask[b*T + t] : 1.f;
    for (int c = ty; c < C; c += 8) {
        size_t idx = ((size_t)b*C + c)*T + t;
        float v = hbuf[idx] + yv[idx];
        hbuf[idx] = ((v - m)*r*g[c] + bb[c]) * mk;
    }
}

// ---------------- launch -------------------------------------------------------
extern "C" void kernel_launch(void* const* d_in, const int* in_sizes, int n_in,
                              void* d_out, int out_size) {
    const int*   x    = (const int*)d_in[0];
    const int*   xlen = (const int*)d_in[1];
    const float* emb  = (const float*)d_in[2];
    const float* Wq = (const float*)d_in[3],  *bq = (const float*)d_in[4];
    const float* Wk = (const float*)d_in[5],  *bk = (const float*)d_in[6];
    const float* Wv = (const float*)d_in[7],  *bv = (const float*)d_in[8];
    const float* Wo = (const float*)d_in[9],  *bo = (const float*)d_in[10];
    const float* rel_k = (const float*)d_in[11], *rel_v = (const float*)d_in[12];
    const float* ln1g = (const float*)d_in[13], *ln1b = (const float*)d_in[14];
    const float* ln2g = (const float*)d_in[15], *ln2b = (const float*)d_in[16];
    const float* w1 = (const float*)d_in[17], *b1 = (const float*)d_in[18];
    const float* w2 = (const float*)d_in[19], *b2 = (const float*)d_in[20];
    const float* pw = (const float*)d_in[21], *pbv = (const float*)d_in[22];
    float* out = (float*)d_out;
    size_t SZ = (size_t)B*C*T;

    float *ph,*pqkv,*pctx,*py,*pp,*pf,*pb3;
    u32 *x5h,*x5l,*x2h,*x2l,*wqh,*wql,*woh,*wol,*w1h,*w1l,*w2h,*w2l,*pjh,*pjl;
    cudaGetSymbolAddress((void**)&ph,   g_h);
    cudaGetSymbolAddress((void**)&pqkv, g_qkv);
    cudaGetSymbolAddress((void**)&pctx, g_ctx);
    cudaGetSymbolAddress((void**)&py,   g_y);
    cudaGetSymbolAddress((void**)&pp,   g_p);
    cudaGetSymbolAddress((void**)&pf,   g_f);
    cudaGetSymbolAddress((void**)&pb3,  g_b3);
    cudaGetSymbolAddress((void**)&x5h,  g_px512_hi);
    cudaGetSymbolAddress((void**)&x5l,  g_px512_lo);
    cudaGetSymbolAddress((void**)&x2h,  g_px2048_hi);
    cudaGetSymbolAddress((void**)&x2l,  g_px2048_lo);
    cudaGetSymbolAddress((void**)&wqh,  g_wqkv_hi);
    cudaGetSymbolAddress((void**)&wql,  g_wqkv_lo);
    cudaGetSymbolAddress((void**)&woh,  g_wo_hi);
    cudaGetSymbolAddress((void**)&wol,  g_wo_lo);
    cudaGetSymbolAddress((void**)&w1h,  g_w1_hi);
    cudaGetSymbolAddress((void**)&w1l,  g_w1_lo);
    cudaGetSymbolAddress((void**)&w2h,  g_w2_hi);
    cudaGetSymbolAddress((void**)&w2l,  g_w2_lo);
    cudaGetSymbolAddress((void**)&pjh,  g_pj_hi);
    cudaGetSymbolAddress((void**)&pjl,  g_pj_lo);

    const int SMB = 64*136*2*4;   // 69632 bytes, double-buffered B
    static int attr_set = 0;
    if (!attr_set) {
        cudaFuncSetAttribute(k_mma_f<1,128>, cudaFuncAttributeMaxDynamicSharedMemorySize, SMB);
        cudaFuncSetAttribute(k_mma_f<3,128>, cudaFuncAttributeMaxDynamicSharedMemorySize, SMB);
        attr_set = 1;
    }

    dim3 tb(32,8);
    k_embed<<<dim3(T/32, B), dim3(32,8)>>>(x, xlen, emb, out, out + 4*SZ);
    // proj weights once (fused 1024 x 512)
    k_packwf<<<dim3(8, 32, 1), 256>>>(pw, 1.f, pjh, pjl, C, 1, 32, 8, 0);

    for (int i = 0; i < LYR; i++) {
        k_packwf<<<dim3(4, 32, 1), 256>>>(Wq + (size_t)i*C*C, 0.125f, wqh, wql, C, 1, 32, 12, 0);
        k_packwf<<<dim3(4, 32, 1), 256>>>(Wk + (size_t)i*C*C, 1.f,    wqh, wql, C, 1, 32, 12, 4);
        k_packwf<<<dim3(4, 32, 1), 256>>>(Wv + (size_t)i*C*C, 1.f,    wqh, wql, C, 1, 32, 12, 8);
        k_packwf<<<dim3(4, 32, 1), 256>>>(Wo + (size_t)i*C*C, 1.f,    woh, wol, C, 1, 32, 4, 0);
        k_packwf<<<dim3(16, 32, 3), 256>>>(w1 + (size_t)i*DFF*C*3, 1.f, w1h, w1l, C*3, 3, 32, 16, 0);
        k_packwf<<<dim3(4, 128, 3), 256>>>(w2 + (size_t)i*C*DFF*3, 1.f, w2h, w2l, DFF*3, 3, 128, 4, 0);
        k_bias3<<<6, 256>>>(bq + i*C, bk + i*C, bv + i*C, pb3);

        k_packx<<<dim3(8, 8, B), 256>>>(ph, x5h, x5l, C, 0);
        k_mma_f<1,128><<<dim3(4, 12, B), 256, SMB>>>(wqh, wql, x5h, x5l, pb3,
            pqkv, pqkv, 1536, C, 0, 0);
        k_qk<<<dim3(T/64, T/128, B*H), 256>>>(pqkv, pp);
        k_relband<<<dim3(T/32, H, B), tb>>>(pqkv, pp, rel_k + (size_t)i*NREL*DK);
        k_softmax<<<dim3(T, H, B), 256>>>(pp);
        k_ctx<<<dim3(T/128, B*H), 256>>>(pp, pqkv, pctx, rel_v + (size_t)i*NREL*DK);
        k_packx<<<dim3(8, 8, B), 256>>>(pctx, x5h, x5l, C, 0);
        k_mma_f<1,128><<<dim3(4, 4, B), 256, SMB>>>(woh, wol, x5h, x5l, bo + i*C,
            py, py, C, C, 0, 0);
        k_ln<<<dim3(T/32, B), tb>>>(ph, py, ln1g + i*C, ln1b + i*C, 0);

        k_packx<<<dim3(8, 8, B), 256>>>(ph, x5h, x5l, C, 1);
        k_mma_f<3,128><<<dim3(4, 16, B), 256, SMB>>>(w1h, w1l, x5h, x5l, b1 + i*DFF,
            pf, pf, DFF, C, 1, 0);
        k_packx<<<dim3(8, 32, B), 256>>>(pf, x2h, x2l, DFF, 1);
        k_mma_f<3,128><<<dim3(4, 4, B), 256, SMB>>>(w2h, w2l, x2h, x2l, b2 + i*C,
            py, py, C, DFF, 0, 1);
        k_ln<<<dim3(T/32, B), tb>>>(ph, py, ln2g + i*C, ln2b + i*C, 1);
    }

    k_copy4<<<(B*C*T)/1024, 256>>>((const float4*)ph, (float4*)(out + SZ));
    k_packx<<<dim3(8, 8, B), 256>>>(ph, x5h, x5l, C, 0);
    k_mma_f<1,128><<<dim3(4, 8, B), 256, SMB>>>(pjh, pjl, x5h, x5l, pbv,
        out + 2*SZ, out + 3*SZ, 512, C, 0, 1);
}